// round 10
// baseline (speedup 1.0000x reference)
#include <cuda_runtime.h>
#include <math.h>

#define LL 768
#define CS 256
#define CZ 128
#define NH 8
#define FEAT 544
#define NPROJ 1152
#define ATTN_OFF (LL*CS)

#define OFF_Q   0
#define OFF_K   256
#define OFF_V   512
#define OFF_QPL 768
#define OFF_KPL 864
#define OFF_VPL 960

typedef unsigned long long ull;

__device__ float g_sln[LL*CS];
__device__ float g_Wcat[CS*NPROJ];
__device__ float g_proj[LL*NPROJ];
__device__ float g_kt[CS*LL];            // [c][j]
__device__ float g_qpg[LL*96];           // [i][h*12+pp]
__device__ float g_kpgt[96*LL];          // [(h*12+pp)][j]
__device__ float g_vpg[LL*192];          // [j][h*24+pp]
__device__ float g_qn[LL*NH];
__device__ float g_knt[NH*LL];
__device__ float g_pb[(long)NH*LL*LL];   // [h][i][j]
__device__ float g_pv[(long)LL*LL*32];   // [pair][h*4+d]
__device__ float g_feat[LL*FEAT];
__device__ float g_ptg[LL*192];
__device__ float g_T1[40];
__device__ float g_T0[40];
__device__ ull g_Wz[CZ*20];              // lnw-folded f32x2-packed z weights

__device__ __forceinline__ ull pk2(float lo, float hi){
    ull r; asm("mov.b64 %0,{%1,%2};":"=l"(r):"f"(lo),"f"(hi)); return r;
}
__device__ __forceinline__ void fma2(ull &d, ull a, ull b){
    asm("fma.rn.f32x2 %0, %1, %2, %0;" : "+l"(d) : "l"(a), "l"(b));
}
__device__ __forceinline__ float2 upk2(ull v){
    float2 r; asm("mov.b64 {%0,%1},%2;":"=f"(r.x),"=f"(r.y):"l"(v)); return r;
}

// ---- LN of s ----
__global__ __launch_bounds__(256) void k_ln_s(const float* __restrict__ s,
                                              const float* __restrict__ w,
                                              const float* __restrict__ b){
    int i = blockIdx.x, t = threadIdx.x;
    float x = s[i*CS + t];
    __shared__ float sh[8]; __shared__ float s_m, s_r;
    float v = x;
    #pragma unroll
    for (int o=16;o;o>>=1) v += __shfl_xor_sync(~0u,v,o);
    if ((t&31)==0) sh[t>>5]=v;
    __syncthreads();
    if (t==0){ float u=0; for(int kk=0;kk<8;kk++)u+=sh[kk]; s_m=u*(1.f/256.f); }
    __syncthreads();
    float d = x - s_m; v = d*d;
    #pragma unroll
    for (int o=16;o;o>>=1) v += __shfl_xor_sync(~0u,v,o);
    if ((t&31)==0) sh[t>>5]=v;
    __syncthreads();
    if (t==0){ float u=0; for(int kk=0;kk<8;kk++)u+=sh[kk]; s_r=rsqrtf(u*(1.f/256.f)+1e-5f); }
    __syncthreads();
    g_sln[i*CS+t] = d*s_r*w[t] + b[t];
}

// ---- premix ----
__global__ void k_premix(const float* __restrict__ lnw, const float* __restrict__ lnb,
                         const float* __restrict__ Wpb, const float* __restrict__ Wpo){
    int idx = blockIdx.x*256 + threadIdx.x;
    if (idx < 2560){
        int c = idx/20, np = idx%20, n = np*2;
        float w0 = lnw[c]*((n  <8)?Wpb[c*8+n  ]:Wpo[c*32+n-8]);
        float w1 = lnw[c]*((n+1<8)?Wpb[c*8+n+1]:Wpo[c*32+n-7]);
        g_Wz[idx] = pk2(w0,w1);
    } else if (idx < 2600){
        int n = idx-2560;
        float t1=0.f, t0=0.f;
        for(int c=0;c<CZ;c++){
            float wv = (n<8)?Wpb[c*8+n]:Wpo[c*32+n-8];
            t1 += lnw[c]*wv; t0 += lnb[c]*wv;
        }
        g_T1[n]=t1; g_T0[n]=t0;
    }
}

// ---- concat projection weights ----
__global__ __launch_bounds__(256) void k_wcat(const float* __restrict__ Wq, const float* __restrict__ Wk,
                                              const float* __restrict__ Wv, const float* __restrict__ Wqp,
                                              const float* __restrict__ Wkp, const float* __restrict__ Wvp){
    int idx = blockIdx.x*256 + threadIdx.x;
    int k = idx/NPROJ, n = idx%NPROJ;
    float v;
    if      (n < 256)  v = Wq [k*256 + n];
    else if (n < 512)  v = Wk [k*256 + n-256];
    else if (n < 768)  v = Wv [k*256 + n-512];
    else if (n < 864)  v = Wqp[k*96  + n-768];
    else if (n < 960)  v = Wkp[k*96  + n-864];
    else               v = Wvp[k*192 + n-960];
    g_Wcat[idx] = v;
}

// ---- SGEMM ----
__global__ __launch_bounds__(256) void k_sgemm2(const float* __restrict__ A,
                                                const float* __restrict__ W,
                                                const float* __restrict__ bias,
                                                const float* __restrict__ msk,
                                                float* __restrict__ C,
                                                int M, int N, int K){
    __shared__ float As[16][68], Bs[16][68];
    int tid = threadIdx.x;
    int tx = tid&15, ty = tid>>4;
    const float* Ab = A + (long)(blockIdx.y*64)*K;
    const float* Wb = W + blockIdx.x*64;
    float acc[4][4];
    #pragma unroll
    for(int u=0;u<4;u++)
        #pragma unroll
        for(int w2=0;w2<4;w2++) acc[u][w2]=0.f;

    int ar = tid>>2, ak = (tid&3)*4;
    int bk = tid>>4, bn = (tid&15)*4;
    float4 a4 = *(const float4*)&Ab[ar*K + ak];
    float4 b4 = *(const float4*)&Wb[(long)bk*N + bn];

    for(int k0=0;k0<K;k0+=16){
        As[ak+0][ar]=a4.x; As[ak+1][ar]=a4.y; As[ak+2][ar]=a4.z; As[ak+3][ar]=a4.w;
        *(float4*)&Bs[bk][bn]=b4;
        __syncthreads();
        if (k0+16 < K){
            a4 = *(const float4*)&Ab[ar*K + k0+16 + ak];
            b4 = *(const float4*)&Wb[(long)(k0+16+bk)*N + bn];
        }
        #pragma unroll
        for(int kk=0;kk<16;kk++){
            float4 av=*(const float4*)&As[kk][ty*4];
            float4 bv=*(const float4*)&Bs[kk][tx*4];
            float aa[4]={av.x,av.y,av.z,av.w};
            float bb[4]={bv.x,bv.y,bv.z,bv.w};
            #pragma unroll
            for(int u=0;u<4;u++)
                #pragma unroll
                for(int w2=0;w2<4;w2++) acc[u][w2] += aa[u]*bb[w2];
        }
        __syncthreads();
    }
    int gm0 = blockIdx.y*64 + ty*4, gn0 = blockIdx.x*64 + tx*4;
    #pragma unroll
    for(int u=0;u<4;u++){
        int gm = gm0+u;
        float mv = msk ? msk[gm] : 1.f;
        #pragma unroll
        for(int w2=0;w2<4;w2++){
            int gn = gn0+w2;
            float vv = acc[u][w2];
            if (bias) vv += bias[gn];
            C[(long)gm*N+gn] = vv*mv;
        }
    }
}

// ---- transpose k ----
__global__ __launch_bounds__(256) void k_transpose_k(){
    __shared__ float tile[32][33];
    int c0=blockIdx.x*32, j0=blockIdx.y*32;
    int tx=threadIdx.x&31, ty=threadIdx.x>>5;
    for(int r=ty;r<32;r+=8) tile[r][tx]=g_proj[(j0+r)*NPROJ + OFF_K + c0+tx];
    __syncthreads();
    for(int r=ty;r<32;r+=8) g_kt[(c0+r)*LL+j0+tx]=tile[tx][r];
}

// ---- rigid transform ----
__global__ __launch_bounds__(128) void k_transform(const float* __restrict__ R,
                                                   const float* __restrict__ t){
    int i=blockIdx.x, tid=threadIdx.x;
    __shared__ float Rl[9], tl[3];
    if(tid<9) Rl[tid]=R[i*9+tid];
    if(tid<3) tl[tid]=t[i*3+tid];
    __syncthreads();
    if (tid<32){
        const float* src = g_proj + i*NPROJ + OFF_QPL + tid*3;
        float p0=src[0], p1=src[1], p2=src[2];
        float gx=Rl[0]*p0+Rl[1]*p1+Rl[2]*p2+tl[0];
        float gy=Rl[3]*p0+Rl[4]*p1+Rl[5]*p2+tl[1];
        float gz=Rl[6]*p0+Rl[7]*p1+Rl[8]*p2+tl[2];
        g_qpg[i*96+tid*3]=gx; g_qpg[i*96+tid*3+1]=gy; g_qpg[i*96+tid*3+2]=gz;
        float sq=gx*gx+gy*gy+gz*gz;
        sq += __shfl_xor_sync(~0u,sq,1); sq += __shfl_xor_sync(~0u,sq,2);
        if((tid&3)==0) g_qn[i*NH+(tid>>2)]=sq;
    } else if (tid<64){
        int idx=tid-32;
        const float* src = g_proj + i*NPROJ + OFF_KPL + idx*3;
        float p0=src[0], p1=src[1], p2=src[2];
        float gx=Rl[0]*p0+Rl[1]*p1+Rl[2]*p2+tl[0];
        float gy=Rl[3]*p0+Rl[4]*p1+Rl[5]*p2+tl[1];
        float gz=Rl[6]*p0+Rl[7]*p1+Rl[8]*p2+tl[2];
        g_kpgt[(idx*3+0)*LL+i]=gx; g_kpgt[(idx*3+1)*LL+i]=gy; g_kpgt[(idx*3+2)*LL+i]=gz;
        float sq=gx*gx+gy*gy+gz*gz;
        sq += __shfl_xor_sync(~0u,sq,1); sq += __shfl_xor_sync(~0u,sq,2);
        if((idx&3)==0) g_knt[(idx>>2)*LL+i]=sq;
    } else {
        int idx=tid-64;
        const float* src = g_proj + i*NPROJ + OFF_VPL + idx*3;
        float p0=src[0], p1=src[1], p2=src[2];
        g_vpg[i*192+idx*3+0]=Rl[0]*p0+Rl[1]*p1+Rl[2]*p2+tl[0];
        g_vpg[i*192+idx*3+1]=Rl[3]*p0+Rl[4]*p1+Rl[5]*p2+tl[1];
        g_vpg[i*192+idx*3+2]=Rl[6]*p0+Rl[7]*p1+Rl[8]*p2+tl[2];
    }
}

// ---- z pass: LN folded, z read once -> pair_bias + pair_v
//      z staged PRE-DUPLICATED as f32x2 pairs (no pack MOVs in inner loop) ----
#define ZSTR 265
__global__ __launch_bounds__(256) void k_zpass(const float* __restrict__ z){
    __shared__ __align__(16) float U[256*41];       // union: Zs2 (ull[16*265]=33.9KB) / Os (42KB)
    __shared__ __align__(16) ull Ws[16][24];
    __shared__ float s_mean[256], s_rstd[256], T1s[40], T0s[40];
    ull* Zs2 = (ull*)U;
    float (*Os)[41] = (float(*)[41])U;
    int tid=threadIdx.x;
    long pair0=(long)blockIdx.x*256;
    if(tid<40){ T1s[tid]=g_T1[tid]; T0s[tid]=g_T0[tid]; }

    int tx=tid&63, ty=tid>>6;      // thread owns rows tx, tx+64, tx+128, tx+192; cols ty*10..+9
    ull acc2[4][5];
    #pragma unroll
    for(int m=0;m<4;m++)
        #pragma unroll
        for(int n=0;n<5;n++) acc2[m][n]=0ull;

    int rq=tid>>2, kq=tid&3;
    float sums[4]={0,0,0,0}, sqs[4]={0,0,0,0};
    float4 pf[4];
    #pragma unroll
    for(int i=0;i<4;i++) pf[i]=*(const float4*)&z[(pair0+rq+64*i)*CZ + kq*4];

    for(int k0=0;k0<CZ;k0+=16){
        #pragma unroll
        for(int i=0;i<4;i++){
            float4 v=pf[i];
            sums[i]+=v.x+v.y+v.z+v.w;
            sqs[i]+=v.x*v.x+v.y*v.y+v.z*v.z+v.w*v.w;
            int row=rq+64*i, kkb=kq*4;
            Zs2[(kkb+0)*ZSTR+row]=pk2(v.x,v.x);
            Zs2[(kkb+1)*ZSTR+row]=pk2(v.y,v.y);
            Zs2[(kkb+2)*ZSTR+row]=pk2(v.z,v.z);
            Zs2[(kkb+3)*ZSTR+row]=pk2(v.w,v.w);
        }
        {   // stage 16x20 weights into 6-stride padded groups
            int l0=tid, l1=tid+256;
            int kk0=l0>>5, np0=l0&31;
            if(np0<20) Ws[kk0][(np0/5)*6 + (np0%5)]=g_Wz[(k0+kk0)*20+np0];
            int kk1=l1>>5, np1=l1&31;
            if(np1<20) Ws[kk1][(np1/5)*6 + (np1%5)]=g_Wz[(k0+kk1)*20+np1];
        }
        __syncthreads();
        if(k0+16<CZ){
            #pragma unroll
            for(int i=0;i<4;i++) pf[i]=*(const float4*)&z[(pair0+rq+64*i)*CZ + k0+16 + kq*4];
        }
        #pragma unroll
        for(int kk=0;kk<16;kk++){
            const ull* zr = &Zs2[kk*ZSTR];
            ull z0=zr[tx], z1=zr[tx+64], z2=zr[tx+128], z3=zr[tx+192];
            const ull* wrow=&Ws[kk][ty*6];
            ulonglong2 wab = *(const ulonglong2*)(wrow);
            ulonglong2 wcd = *(const ulonglong2*)(wrow+2);
            ull we = wrow[4];
            ull wv[5]={wab.x,wab.y,wcd.x,wcd.y,we};
            #pragma unroll
            for(int nn=0;nn<5;nn++){
                fma2(acc2[0][nn],z0,wv[nn]);
                fma2(acc2[1][nn],z1,wv[nn]);
                fma2(acc2[2][nn],z2,wv[nn]);
                fma2(acc2[3][nn],z3,wv[nn]);
            }
        }
        __syncthreads();
    }
    #pragma unroll
    for(int i=0;i<4;i++){
        sums[i]+=__shfl_xor_sync(~0u,sums[i],1); sums[i]+=__shfl_xor_sync(~0u,sums[i],2);
        sqs[i] +=__shfl_xor_sync(~0u,sqs[i],1);  sqs[i] +=__shfl_xor_sync(~0u,sqs[i],2);
    }
    if(kq==0){
        #pragma unroll
        for(int i=0;i<4;i++){
            float m=sums[i]*(1.f/128.f);
            s_mean[rq+64*i]=m;
            s_rstd[rq+64*i]=rsqrtf(sqs[i]*(1.f/128.f)-m*m+1e-5f);
        }
    }
    __syncthreads();
    #pragma unroll
    for(int rr=0;rr<4;rr++){
        int r=tx+64*rr;
        float rs=s_rstd[r], mn=s_mean[r];
        #pragma unroll
        for(int nn=0;nn<5;nn++){
            float2 a=upk2(acc2[rr][nn]);
            int n=ty*10+nn*2;
            Os[r][n]  =rs*(a.x-mn*T1s[n])  +T0s[n];
            Os[r][n+1]=rs*(a.y-mn*T1s[n+1])+T0s[n+1];
        }
    }
    __syncthreads();
    for(int l=tid;l<2048;l+=256){
        int hh=l>>8, r=l&255;
        long p=pair0+r; int i=(int)(p/LL), j=(int)(p%LL);
        g_pb[((long)hh*LL+i)*LL+j]=Os[r][hh];
    }
    for(int l=tid;l<8192;l+=256){
        int r=l>>5, o=l&31;
        g_pv[(pair0+r)*32+o]=Os[r][8+o];
    }
}

// ---- fused logits + softmax -> attn ----
__global__ __launch_bounds__(256) void k_logits_softmax(const float* __restrict__ mask,
                                                        const float* __restrict__ pweights,
                                                        float* __restrict__ attn){
    int h=blockIdx.y, i0=blockIdx.x*4, tid=threadIdx.x;
    __shared__ float qv[4][32], qp[4][12], qnv[4], mi[4], red[8][4], bmax[4], brcp[4], s_pw;
    if(tid<128){ int ii=tid>>5, c=tid&31; qv[ii][c]=g_proj[(i0+ii)*NPROJ + OFF_Q + h*32+c]; }
    else if(tid<176){ int l=tid-128, ii=l/12, pp=l%12; qp[ii][pp]=g_qpg[(i0+ii)*96+h*12+pp]; }
    else if(tid<180){ int ii=tid-176; qnv[ii]=g_qn[(i0+ii)*NH+h]; mi[ii]=mask[i0+ii]; }
    else if(tid==180){ float xw=pweights[h]; s_pw=0.5f*log1pf(expf(xw)); }
    __syncthreads();

    float lv[3][4];
    const float invs = 0.17677669529663687f;
    #pragma unroll
    for(int jj=0;jj<3;jj++){
        int j=jj*256+tid;
        float sl[4]={0,0,0,0};
        const float* kt = g_kt + h*32*LL + j;
        #pragma unroll
        for(int c=0;c<32;c++){
            float kc=kt[c*LL];
            sl[0]+=qv[0][c]*kc; sl[1]+=qv[1][c]*kc; sl[2]+=qv[2][c]*kc; sl[3]+=qv[3][c]*kc;
        }
        float pd[4]={0,0,0,0};
        const float* kp = g_kpgt + h*12*LL + j;
        #pragma unroll
        for(int pp=0;pp<12;pp++){
            float kc=kp[pp*LL];
            pd[0]+=qp[0][pp]*kc; pd[1]+=qp[1][pp]*kc; pd[2]+=qp[2][pp]*kc; pd[3]+=qp[3][pp]*kc;
        }
        float knj=g_knt[h*LL+j], mj=mask[j];
        const float* pbp = g_pb + ((long)h*LL+i0)*LL + j;
        #pragma unroll
        for(int ii=0;ii<4;ii++){
            float lg = sl[ii]*invs + pbp[(long)ii*LL] - s_pw*(qnv[ii]+knj-2.f*pd[ii]);
            if (mi[ii]*mj==0.f) lg=-1e9f;
            lv[jj][ii]=lg;
        }
    }
    #pragma unroll
    for(int ii=0;ii<4;ii++){
        float m=fmaxf(fmaxf(lv[0][ii],lv[1][ii]),lv[2][ii]);
        #pragma unroll
        for(int o=16;o;o>>=1) m=fmaxf(m,__shfl_xor_sync(~0u,m,o));
        if((tid&31)==0) red[tid>>5][ii]=m;
    }
    __syncthreads();
    if(tid<4){ float m=red[0][tid]; for(int w=1;w<8;w++)m=fmaxf(m,red[w][tid]); bmax[tid]=m; }
    __syncthreads();
    float ev[3][4], sm[4]={0,0,0,0};
    #pragma unroll
    for(int jj=0;jj<3;jj++)
        #pragma unroll
        for(int ii=0;ii<4;ii++){ float e=__expf(lv[jj][ii]-bmax[ii]); ev[jj][ii]=e; sm[ii]+=e; }
    __syncthreads();
    #pragma unroll
    for(int ii=0;ii<4;ii++){
        float s=sm[ii];
        #pragma unroll
        for(int o=16;o;o>>=1) s+=__shfl_xor_sync(~0u,s,o);
        if((tid&31)==0) red[tid>>5][ii]=s;
    }
    __syncthreads();
    if(tid<4){ float s=0; for(int w=0;w<8;w++)s+=red[w][tid]; brcp[tid]=1.f/s; }
    __syncthreads();
    #pragma unroll
    for(int jj=0;jj<3;jj++){
        int j=jj*256+tid;
        #pragma unroll
        for(int ii=0;ii<4;ii++)
            attn[((long)h*LL+i0+ii)*LL+j]=ev[jj][ii]*brcp[ii];
    }
}

// ---- fused attn @ [V | v_pts_global] ----
__global__ __launch_bounds__(256) void k_attn_fused(const float* __restrict__ attn,
                                                    const float* __restrict__ V1,
                                                    const float* __restrict__ V2){
    int h=blockIdx.y, i0=blockIdx.x*16, tid=threadIdx.x;
    __shared__ float As[16][33], Vs[32][64];
    int n=tid&63, iw=tid>>6;
    float a0=0.f,a1=0.f,a2=0.f,a3=0.f;
    for(int j0=0;j0<LL;j0+=32){
        for(int l=tid;l<512;l+=256){
            int r=l>>5, jj=l&31;
            As[r][jj]=attn[((long)h*LL+i0+r)*LL+j0+jj];
        }
        for(int l=tid;l<2048;l+=256){
            int r=l>>6, c=l&63;
            float v;
            if (c<32)      v = V1[(long)(j0+r)*NPROJ + h*32 + c];
            else if (c<56) v = V2[(long)(j0+r)*192   + h*24 + (c-32)];
            else           v = 0.f;
            Vs[r][c]=v;
        }
        __syncthreads();
        #pragma unroll
        for(int jj=0;jj<32;jj++){
            float vv=Vs[jj][n];
            a0+=As[iw][jj]*vv; a1+=As[iw+4][jj]*vv;
            a2+=As[iw+8][jj]*vv; a3+=As[iw+12][jj]*vv;
        }
        __syncthreads();
    }
    if (n<32){
        g_feat[(i0+iw)   *FEAT + h*32+n]=a0;
        g_feat[(i0+iw+4) *FEAT + h*32+n]=a1;
        g_feat[(i0+iw+8) *FEAT + h*32+n]=a2;
        g_feat[(i0+iw+12)*FEAT + h*32+n]=a3;
    } else if (n<56){
        int c=n-32;
        g_ptg[(i0+iw)   *192 + h*24+c]=a0;
        g_ptg[(i0+iw+4) *192 + h*24+c]=a1;
        g_ptg[(i0+iw+8) *192 + h*24+c]=a2;
        g_ptg[(i0+iw+12)*192 + h*24+c]=a3;
    }
}

// ---- pair_out ----
__global__ __launch_bounds__(256) void k_pair_out(const float* __restrict__ attn){
    int i=blockIdx.x, tid=threadIdx.x;
    int o=tid&31, jw=tid>>5, h=o>>2;
    float acc=0.f;
    for(int j=jw;j<LL;j+=8)
        acc += attn[((long)h*LL+i)*LL+j]*g_pv[((long)i*LL+j)*32+o];
    __shared__ float red[8][32];
    red[jw][o]=acc;
    __syncthreads();
    if(tid<32){
        float s=0; for(int w=0;w<8;w++)s+=red[w][tid];
        g_feat[i*FEAT+512+tid]=s;
    }
}

// ---- back to local frame + norms ----
__global__ __launch_bounds__(64) void k_local(const float* __restrict__ R,
                                              const float* __restrict__ t){
    int i=blockIdx.x, tid=threadIdx.x;
    __shared__ float Rl[9], tl[3];
    if(tid<9) Rl[tid]=R[i*9+tid];
    if(tid<3) tl[tid]=t[i*3+tid];
    __syncthreads();
    float gx=g_ptg[i*192+tid*3]  -tl[0];
    float gy=g_ptg[i*192+tid*3+1]-tl[1];
    float gz=g_ptg[i*192+tid*3+2]-tl[2];
    float lx=Rl[0]*gx+Rl[3]*gy+Rl[6]*gz;
    float ly=Rl[1]*gx+Rl[4]*gy+Rl[7]*gz;
    float lz=Rl[2]*gx+Rl[5]*gy+Rl[8]*gz;
    g_feat[i*FEAT+256+tid*3]  =lx;
    g_feat[i*FEAT+256+tid*3+1]=ly;
    g_feat[i*FEAT+256+tid*3+2]=lz;
    g_feat[i*FEAT+448+tid]=sqrtf(lx*lx+ly*ly+lz*lz+1e-8f);
}

extern "C" void kernel_launch(void* const* d_in, const int* in_sizes, int n_in,
                              void* d_out, int out_size){
    const float* s      =(const float*)d_in[0];
    const float* z      =(const float*)d_in[1];
    const float* R      =(const float*)d_in[2];
    const float* t      =(const float*)d_in[3];
    const float* mask   =(const float*)d_in[4];
    const float* ln_s_w =(const float*)d_in[5];
    const float* ln_s_b =(const float*)d_in[6];
    const float* ln_z_w =(const float*)d_in[7];
    const float* ln_z_b =(const float*)d_in[8];
    const float* Wq     =(const float*)d_in[9];
    const float* Wk     =(const float*)d_in[10];
    const float* Wv     =(const float*)d_in[11];
    const float* Wpb    =(const float*)d_in[12];
    const float* Wq_pts =(const float*)d_in[13];
    const float* Wk_pts =(const float*)d_in[14];
    const float* Wv_pts =(const float*)d_in[15];
    const float* pw     =(const float*)d_in[16];
    const float* Wpo    =(const float*)d_in[17];
    const float* W_out  =(const float*)d_in[18];
    const float* b_out  =(const float*)d_in[19];
    float* out  = (float*)d_out;
    float* attn = out + ATTN_OFF;

    float *p_sln,*p_wcat,*p_proj,*p_vpg,*p_feat;
    cudaGetSymbolAddress((void**)&p_sln,  g_sln);
    cudaGetSymbolAddress((void**)&p_wcat, g_Wcat);
    cudaGetSymbolAddress((void**)&p_proj, g_proj);
    cudaGetSymbolAddress((void**)&p_vpg,  g_vpg);
    cudaGetSymbolAddress((void**)&p_feat, g_feat);

    static cudaStream_t sB = nullptr;
    static cudaEvent_t evF1=nullptr, evJ1=nullptr, evF2=nullptr, evJ2=nullptr;
    if (sB == nullptr){
        cudaStreamCreateWithFlags(&sB, cudaStreamNonBlocking);
        cudaEventCreateWithFlags(&evF1, cudaEventDisableTiming);
        cudaEventCreateWithFlags(&evJ1, cudaEventDisableTiming);
        cudaEventCreateWithFlags(&evF2, cudaEventDisableTiming);
        cudaEventCreateWithFlags(&evJ2, cudaEventDisableTiming);
    }

    // fork 1: projection chain (sB) || z pass (s0)
    cudaEventRecord(evF1, 0);
    cudaStreamWaitEvent(sB, evF1, 0);

    k_ln_s<<<LL,256,0,sB>>>(s, ln_s_w, ln_s_b);
    k_wcat<<<(CS*NPROJ)/256,256,0,sB>>>(Wq, Wk, Wv, Wq_pts, Wk_pts, Wv_pts);
    k_sgemm2<<<dim3(NPROJ/64, LL/64),256,0,sB>>>(p_sln, p_wcat, nullptr, nullptr, p_proj, LL, NPROJ, CS);
    k_transpose_k<<<dim3(8,24),256,0,sB>>>();
    k_transform<<<LL,128,0,sB>>>(R, t);
    cudaEventRecord(evJ1, sB);

    k_premix<<<11,256>>>(ln_z_w, ln_z_b, Wpb, Wpo);
    k_zpass<<<(LL*LL)/256,256>>>(z);

    cudaStreamWaitEvent(0, evJ1, 0);
    k_logits_softmax<<<dim3(LL/4,NH),256>>>(mask, pw, attn);

    // fork 2: attn_fused + local (sB) || pair_out (s0)
    cudaEventRecord(evF2, 0);
    cudaStreamWaitEvent(sB, evF2, 0);
    k_attn_fused<<<dim3(LL/16,NH),256,0,sB>>>(attn, p_proj + OFF_V, p_vpg);
    k_local<<<LL,64,0,sB>>>(R, t);
    cudaEventRecord(evJ2, sB);

    k_pair_out<<<LL,256>>>(attn);

    cudaStreamWaitEvent(0, evJ2, 0);
    k_sgemm2<<<dim3(CS/64, LL/64),256>>>(p_feat, W_out, b_out, mask, out, LL, CS, FEAT);
}

// round 11
// speedup vs baseline: 1.0835x; 1.0835x over previous
#include <cuda_runtime.h>
#include <math.h>

#define LL 768
#define CS 256
#define CZ 128
#define NH 8
#define FEAT 544
#define NPROJ 1152
#define ATTN_OFF (LL*CS)

#define OFF_Q   0
#define OFF_K   256
#define OFF_V   512
#define OFF_QPL 768
#define OFF_KPL 864
#define OFF_VPL 960

typedef unsigned long long ull;

__device__ float g_sln[LL*CS];
__device__ float g_Wcat[CS*NPROJ];
__device__ float g_proj[LL*NPROJ];
__device__ float g_kt[CS*LL];            // [c][j]
__device__ float g_qpg[LL*96];           // [i][h*12+pp]
__device__ float g_kpgt[96*LL];          // [(h*12+pp)][j]
__device__ float g_vpg[LL*192];          // [j][h*24+pp]
__device__ float g_qn[LL*NH];
__device__ float g_knt[NH*LL];
__device__ float g_pb[(long)NH*LL*LL];   // [h][i][j]
__device__ float g_pv[(long)LL*LL*32];   // [pair][h*4+d]
__device__ float g_feat[LL*FEAT];
__device__ float g_ptg[LL*192];
__device__ float g_T1[40];
__device__ float g_T0[40];
__device__ ull g_Wz[CZ*20];              // lnw-folded f32x2-packed z weights

__device__ __forceinline__ ull pk2(float lo, float hi){
    ull r; asm("mov.b64 %0,{%1,%2};":"=l"(r):"f"(lo),"f"(hi)); return r;
}
__device__ __forceinline__ void fma2(ull &d, ull a, ull b){
    asm("fma.rn.f32x2 %0, %1, %2, %0;" : "+l"(d) : "l"(a), "l"(b));
}
__device__ __forceinline__ float2 upk2(ull v){
    float2 r; asm("mov.b64 {%0,%1},%2;":"=f"(r.x),"=f"(r.y):"l"(v)); return r;
}

// ---- LN of s ----
__global__ __launch_bounds__(256) void k_ln_s(const float* __restrict__ s,
                                              const float* __restrict__ w,
                                              const float* __restrict__ b){
    int i = blockIdx.x, t = threadIdx.x;
    float x = s[i*CS + t];
    __shared__ float sh[8]; __shared__ float s_m, s_r;
    float v = x;
    #pragma unroll
    for (int o=16;o;o>>=1) v += __shfl_xor_sync(~0u,v,o);
    if ((t&31)==0) sh[t>>5]=v;
    __syncthreads();
    if (t==0){ float u=0; for(int kk=0;kk<8;kk++)u+=sh[kk]; s_m=u*(1.f/256.f); }
    __syncthreads();
    float d = x - s_m; v = d*d;
    #pragma unroll
    for (int o=16;o;o>>=1) v += __shfl_xor_sync(~0u,v,o);
    if ((t&31)==0) sh[t>>5]=v;
    __syncthreads();
    if (t==0){ float u=0; for(int kk=0;kk<8;kk++)u+=sh[kk]; s_r=rsqrtf(u*(1.f/256.f)+1e-5f); }
    __syncthreads();
    g_sln[i*CS+t] = d*s_r*w[t] + b[t];
}

// ---- premix ----
__global__ void k_premix(const float* __restrict__ lnw, const float* __restrict__ lnb,
                         const float* __restrict__ Wpb, const float* __restrict__ Wpo){
    int idx = blockIdx.x*256 + threadIdx.x;
    if (idx < 2560){
        int c = idx/20, np = idx%20, n = np*2;
        float w0 = lnw[c]*((n  <8)?Wpb[c*8+n  ]:Wpo[c*32+n-8]);
        float w1 = lnw[c]*((n+1<8)?Wpb[c*8+n+1]:Wpo[c*32+n-7]);
        g_Wz[idx] = pk2(w0,w1);
    } else if (idx < 2600){
        int n = idx-2560;
        float t1=0.f, t0=0.f;
        for(int c=0;c<CZ;c++){
            float wv = (n<8)?Wpb[c*8+n]:Wpo[c*32+n-8];
            t1 += lnw[c]*wv; t0 += lnb[c]*wv;
        }
        g_T1[n]=t1; g_T0[n]=t0;
    }
}

// ---- concat projection weights ----
__global__ __launch_bounds__(256) void k_wcat(const float* __restrict__ Wq, const float* __restrict__ Wk,
                                              const float* __restrict__ Wv, const float* __restrict__ Wqp,
                                              const float* __restrict__ Wkp, const float* __restrict__ Wvp){
    int idx = blockIdx.x*256 + threadIdx.x;
    int k = idx/NPROJ, n = idx%NPROJ;
    float v;
    if      (n < 256)  v = Wq [k*256 + n];
    else if (n < 512)  v = Wk [k*256 + n-256];
    else if (n < 768)  v = Wv [k*256 + n-512];
    else if (n < 864)  v = Wqp[k*96  + n-768];
    else if (n < 960)  v = Wkp[k*96  + n-864];
    else               v = Wvp[k*192 + n-960];
    g_Wcat[idx] = v;
}

// ---- SGEMM ----
__global__ __launch_bounds__(256) void k_sgemm2(const float* __restrict__ A,
                                                const float* __restrict__ W,
                                                const float* __restrict__ bias,
                                                const float* __restrict__ msk,
                                                float* __restrict__ C,
                                                int M, int N, int K){
    __shared__ float As[16][68], Bs[16][68];
    int tid = threadIdx.x;
    int tx = tid&15, ty = tid>>4;
    const float* Ab = A + (long)(blockIdx.y*64)*K;
    const float* Wb = W + blockIdx.x*64;
    float acc[4][4];
    #pragma unroll
    for(int u=0;u<4;u++)
        #pragma unroll
        for(int w2=0;w2<4;w2++) acc[u][w2]=0.f;

    int ar = tid>>2, ak = (tid&3)*4;
    int bk = tid>>4, bn = (tid&15)*4;
    float4 a4 = *(const float4*)&Ab[ar*K + ak];
    float4 b4 = *(const float4*)&Wb[(long)bk*N + bn];

    for(int k0=0;k0<K;k0+=16){
        As[ak+0][ar]=a4.x; As[ak+1][ar]=a4.y; As[ak+2][ar]=a4.z; As[ak+3][ar]=a4.w;
        *(float4*)&Bs[bk][bn]=b4;
        __syncthreads();
        if (k0+16 < K){
            a4 = *(const float4*)&Ab[ar*K + k0+16 + ak];
            b4 = *(const float4*)&Wb[(long)(k0+16+bk)*N + bn];
        }
        #pragma unroll
        for(int kk=0;kk<16;kk++){
            float4 av=*(const float4*)&As[kk][ty*4];
            float4 bv=*(const float4*)&Bs[kk][tx*4];
            float aa[4]={av.x,av.y,av.z,av.w};
            float bb[4]={bv.x,bv.y,bv.z,bv.w};
            #pragma unroll
            for(int u=0;u<4;u++)
                #pragma unroll
                for(int w2=0;w2<4;w2++) acc[u][w2] += aa[u]*bb[w2];
        }
        __syncthreads();
    }
    int gm0 = blockIdx.y*64 + ty*4, gn0 = blockIdx.x*64 + tx*4;
    #pragma unroll
    for(int u=0;u<4;u++){
        int gm = gm0+u;
        float mv = msk ? msk[gm] : 1.f;
        #pragma unroll
        for(int w2=0;w2<4;w2++){
            int gn = gn0+w2;
            float vv = acc[u][w2];
            if (bias) vv += bias[gn];
            C[(long)gm*N+gn] = vv*mv;
        }
    }
}

// ---- transpose k ----
__global__ __launch_bounds__(256) void k_transpose_k(){
    __shared__ float tile[32][33];
    int c0=blockIdx.x*32, j0=blockIdx.y*32;
    int tx=threadIdx.x&31, ty=threadIdx.x>>5;
    for(int r=ty;r<32;r+=8) tile[r][tx]=g_proj[(j0+r)*NPROJ + OFF_K + c0+tx];
    __syncthreads();
    for(int r=ty;r<32;r+=8) g_kt[(c0+r)*LL+j0+tx]=tile[tx][r];
}

// ---- rigid transform ----
__global__ __launch_bounds__(128) void k_transform(const float* __restrict__ R,
                                                   const float* __restrict__ t){
    int i=blockIdx.x, tid=threadIdx.x;
    __shared__ float Rl[9], tl[3];
    if(tid<9) Rl[tid]=R[i*9+tid];
    if(tid<3) tl[tid]=t[i*3+tid];
    __syncthreads();
    if (tid<32){
        const float* src = g_proj + i*NPROJ + OFF_QPL + tid*3;
        float p0=src[0], p1=src[1], p2=src[2];
        float gx=Rl[0]*p0+Rl[1]*p1+Rl[2]*p2+tl[0];
        float gy=Rl[3]*p0+Rl[4]*p1+Rl[5]*p2+tl[1];
        float gz=Rl[6]*p0+Rl[7]*p1+Rl[8]*p2+tl[2];
        g_qpg[i*96+tid*3]=gx; g_qpg[i*96+tid*3+1]=gy; g_qpg[i*96+tid*3+2]=gz;
        float sq=gx*gx+gy*gy+gz*gz;
        sq += __shfl_xor_sync(~0u,sq,1); sq += __shfl_xor_sync(~0u,sq,2);
        if((tid&3)==0) g_qn[i*NH+(tid>>2)]=sq;
    } else if (tid<64){
        int idx=tid-32;
        const float* src = g_proj + i*NPROJ + OFF_KPL + idx*3;
        float p0=src[0], p1=src[1], p2=src[2];
        float gx=Rl[0]*p0+Rl[1]*p1+Rl[2]*p2+tl[0];
        float gy=Rl[3]*p0+Rl[4]*p1+Rl[5]*p2+tl[1];
        float gz=Rl[6]*p0+Rl[7]*p1+Rl[8]*p2+tl[2];
        g_kpgt[(idx*3+0)*LL+i]=gx; g_kpgt[(idx*3+1)*LL+i]=gy; g_kpgt[(idx*3+2)*LL+i]=gz;
        float sq=gx*gx+gy*gy+gz*gz;
        sq += __shfl_xor_sync(~0u,sq,1); sq += __shfl_xor_sync(~0u,sq,2);
        if((idx&3)==0) g_knt[(idx>>2)*LL+i]=sq;
    } else {
        int idx=tid-64;
        const float* src = g_proj + i*NPROJ + OFF_VPL + idx*3;
        float p0=src[0], p1=src[1], p2=src[2];
        g_vpg[i*192+idx*3+0]=Rl[0]*p0+Rl[1]*p1+Rl[2]*p2+tl[0];
        g_vpg[i*192+idx*3+1]=Rl[3]*p0+Rl[4]*p1+Rl[5]*p2+tl[1];
        g_vpg[i*192+idx*3+2]=Rl[6]*p0+Rl[7]*p1+Rl[8]*p2+tl[2];
    }
}

// ---- z pass: LN folded, z read once -> pair_bias + pair_v (R7 exact) ----
__global__ __launch_bounds__(256) void k_zpass(const float* __restrict__ z){
    __shared__ __align__(16) float U[256*41];       // union: Zs[16][264] then Os[256][41]
    __shared__ __align__(16) ull Ws[16][24];        // 4 groups of 5 ull, stride 6
    __shared__ float s_mean[256], s_rstd[256], T1s[40], T0s[40];
    float* Zs = U;
    float (*Os)[41] = (float(*)[41])U;
    int tid=threadIdx.x;
    long pair0=(long)blockIdx.x*256;
    if(tid<40){ T1s[tid]=g_T1[tid]; T0s[tid]=g_T0[tid]; }

    int rbase = (tid&63)*4;
    int ty = tid>>6;
    ull acc2[4][5];
    #pragma unroll
    for(int m=0;m<4;m++)
        #pragma unroll
        for(int n=0;n<5;n++) acc2[m][n]=0ull;

    int rq=tid>>2, kq=tid&3;
    float sums[4]={0,0,0,0}, sqs[4]={0,0,0,0};
    float4 pf[4];
    #pragma unroll
    for(int i=0;i<4;i++) pf[i]=*(const float4*)&z[(pair0+rq+64*i)*CZ + kq*4];

    for(int k0=0;k0<CZ;k0+=16){
        #pragma unroll
        for(int i=0;i<4;i++){
            float4 v=pf[i];
            sums[i]+=v.x+v.y+v.z+v.w;
            sqs[i]+=v.x*v.x+v.y*v.y+v.z*v.z+v.w*v.w;
            int row=rq+64*i, kkb=kq*4;
            Zs[(kkb+0)*264 + (row ^ (((kkb+0)&7)<<2))]=v.x;
            Zs[(kkb+1)*264 + (row ^ (((kkb+1)&7)<<2))]=v.y;
            Zs[(kkb+2)*264 + (row ^ (((kkb+2)&7)<<2))]=v.z;
            Zs[(kkb+3)*264 + (row ^ (((kkb+3)&7)<<2))]=v.w;
        }
        {   // stage 16x20 weights into 6-stride padded groups
            int l0=tid, l1=tid+256;
            int kk0=l0>>5, np0=l0&31;
            if(np0<20) Ws[kk0][(np0/5)*6 + (np0%5)]=g_Wz[(k0+kk0)*20+np0];
            int kk1=l1>>5, np1=l1&31;
            if(np1<20) Ws[kk1][(np1/5)*6 + (np1%5)]=g_Wz[(k0+kk1)*20+np1];
        }
        __syncthreads();
        if(k0+16<CZ){
            #pragma unroll
            for(int i=0;i<4;i++) pf[i]=*(const float4*)&z[(pair0+rq+64*i)*CZ + k0+16 + kq*4];
        }
        #pragma unroll
        for(int kk=0;kk<16;kk++){
            float4 z4=*(const float4*)&Zs[kk*264 + (rbase ^ ((kk&7)<<2))];
            ull zp0=pk2(z4.x,z4.x), zp1=pk2(z4.y,z4.y);
            ull zp2=pk2(z4.z,z4.z), zp3=pk2(z4.w,z4.w);
            const ull* wrow=&Ws[kk][ty*6];
            ulonglong2 wab = *(const ulonglong2*)(wrow);
            ulonglong2 wcd = *(const ulonglong2*)(wrow+2);
            ull we = wrow[4];
            ull wv[5]={wab.x,wab.y,wcd.x,wcd.y,we};
            #pragma unroll
            for(int nn=0;nn<5;nn++){
                fma2(acc2[0][nn],zp0,wv[nn]);
                fma2(acc2[1][nn],zp1,wv[nn]);
                fma2(acc2[2][nn],zp2,wv[nn]);
                fma2(acc2[3][nn],zp3,wv[nn]);
            }
        }
        __syncthreads();
    }
    #pragma unroll
    for(int i=0;i<4;i++){
        sums[i]+=__shfl_xor_sync(~0u,sums[i],1); sums[i]+=__shfl_xor_sync(~0u,sums[i],2);
        sqs[i] +=__shfl_xor_sync(~0u,sqs[i],1);  sqs[i] +=__shfl_xor_sync(~0u,sqs[i],2);
    }
    if(kq==0){
        #pragma unroll
        for(int i=0;i<4;i++){
            float m=sums[i]*(1.f/128.f);
            s_mean[rq+64*i]=m;
            s_rstd[rq+64*i]=rsqrtf(sqs[i]*(1.f/128.f)-m*m+1e-5f);
        }
    }
    __syncthreads();
    #pragma unroll
    for(int rr=0;rr<4;rr++){
        int r=rbase+rr;
        float rs=s_rstd[r], mn=s_mean[r];
        #pragma unroll
        for(int nn=0;nn<5;nn++){
            float2 a=upk2(acc2[rr][nn]);
            int n=ty*10+nn*2;
            Os[r][n]  =rs*(a.x-mn*T1s[n])  +T0s[n];
            Os[r][n+1]=rs*(a.y-mn*T1s[n+1])+T0s[n+1];
        }
    }
    __syncthreads();
    for(int l=tid;l<2048;l+=256){
        int hh=l>>8, r=l&255;
        long p=pair0+r; int i=(int)(p/LL), j=(int)(p%LL);
        g_pb[((long)hh*LL+i)*LL+j]=Os[r][hh];
    }
    for(int l=tid;l<8192;l+=256){
        int r=l>>5, o=l&31;
        g_pv[(pair0+r)*32+o]=Os[r][8+o];
    }
}

// ---- fused logits + softmax -> attn ----
__global__ __launch_bounds__(256) void k_logits_softmax(const float* __restrict__ mask,
                                                        const float* __restrict__ pweights,
                                                        float* __restrict__ attn){
    int h=blockIdx.y, i0=blockIdx.x*4, tid=threadIdx.x;
    __shared__ float qv[4][32], qp[4][12], qnv[4], mi[4], red[8][4], bmax[4], brcp[4], s_pw;
    if(tid<128){ int ii=tid>>5, c=tid&31; qv[ii][c]=g_proj[(i0+ii)*NPROJ + OFF_Q + h*32+c]; }
    else if(tid<176){ int l=tid-128, ii=l/12, pp=l%12; qp[ii][pp]=g_qpg[(i0+ii)*96+h*12+pp]; }
    else if(tid<180){ int ii=tid-176; qnv[ii]=g_qn[(i0+ii)*NH+h]; mi[ii]=mask[i0+ii]; }
    else if(tid==180){ float xw=pweights[h]; s_pw=0.5f*log1pf(expf(xw)); }
    __syncthreads();

    float lv[3][4];
    const float invs = 0.17677669529663687f;
    #pragma unroll
    for(int jj=0;jj<3;jj++){
        int j=jj*256+tid;
        float sl[4]={0,0,0,0};
        const float* kt = g_kt + h*32*LL + j;
        #pragma unroll
        for(int c=0;c<32;c++){
            float kc=kt[c*LL];
            sl[0]+=qv[0][c]*kc; sl[1]+=qv[1][c]*kc; sl[2]+=qv[2][c]*kc; sl[3]+=qv[3][c]*kc;
        }
        float pd[4]={0,0,0,0};
        const float* kp = g_kpgt + h*12*LL + j;
        #pragma unroll
        for(int pp=0;pp<12;pp++){
            float kc=kp[pp*LL];
            pd[0]+=qp[0][pp]*kc; pd[1]+=qp[1][pp]*kc; pd[2]+=qp[2][pp]*kc; pd[3]+=qp[3][pp]*kc;
        }
        float knj=g_knt[h*LL+j], mj=mask[j];
        const float* pbp = g_pb + ((long)h*LL+i0)*LL + j;
        #pragma unroll
        for(int ii=0;ii<4;ii++){
            float lg = sl[ii]*invs + pbp[(long)ii*LL] - s_pw*(qnv[ii]+knj-2.f*pd[ii]);
            if (mi[ii]*mj==0.f) lg=-1e9f;
            lv[jj][ii]=lg;
        }
    }
    #pragma unroll
    for(int ii=0;ii<4;ii++){
        float m=fmaxf(fmaxf(lv[0][ii],lv[1][ii]),lv[2][ii]);
        #pragma unroll
        for(int o=16;o;o>>=1) m=fmaxf(m,__shfl_xor_sync(~0u,m,o));
        if((tid&31)==0) red[tid>>5][ii]=m;
    }
    __syncthreads();
    if(tid<4){ float m=red[0][tid]; for(int w=1;w<8;w++)m=fmaxf(m,red[w][tid]); bmax[tid]=m; }
    __syncthreads();
    float ev[3][4], sm[4]={0,0,0,0};
    #pragma unroll
    for(int jj=0;jj<3;jj++)
        #pragma unroll
        for(int ii=0;ii<4;ii++){ float e=__expf(lv[jj][ii]-bmax[ii]); ev[jj][ii]=e; sm[ii]+=e; }
    __syncthreads();
    #pragma unroll
    for(int ii=0;ii<4;ii++){
        float s=sm[ii];
        #pragma unroll
        for(int o=16;o;o>>=1) s+=__shfl_xor_sync(~0u,s,o);
        if((tid&31)==0) red[tid>>5][ii]=s;
    }
    __syncthreads();
    if(tid<4){ float s=0; for(int w=0;w<8;w++)s+=red[w][tid]; brcp[tid]=1.f/s; }
    __syncthreads();
    #pragma unroll
    for(int jj=0;jj<3;jj++){
        int j=jj*256+tid;
        #pragma unroll
        for(int ii=0;ii<4;ii++)
            attn[((long)h*LL+i0+ii)*LL+j]=ev[jj][ii]*brcp[ii];
    }
}

// ---- fused attn @ [V | v_pts_global] ----
__global__ __launch_bounds__(256) void k_attn_fused(const float* __restrict__ attn,
                                                    const float* __restrict__ V1,
                                                    const float* __restrict__ V2){
    int h=blockIdx.y, i0=blockIdx.x*16, tid=threadIdx.x;
    __shared__ float As[16][33], Vs[32][64];
    int n=tid&63, iw=tid>>6;
    float a0=0.f,a1=0.f,a2=0.f,a3=0.f;
    for(int j0=0;j0<LL;j0+=32){
        for(int l=tid;l<512;l+=256){
            int r=l>>5, jj=l&31;
            As[r][jj]=attn[((long)h*LL+i0+r)*LL+j0+jj];
        }
        for(int l=tid;l<2048;l+=256){
            int r=l>>6, c=l&63;
            float v;
            if (c<32)      v = V1[(long)(j0+r)*NPROJ + h*32 + c];
            else if (c<56) v = V2[(long)(j0+r)*192   + h*24 + (c-32)];
            else           v = 0.f;
            Vs[r][c]=v;
        }
        __syncthreads();
        #pragma unroll
        for(int jj=0;jj<32;jj++){
            float vv=Vs[jj][n];
            a0+=As[iw][jj]*vv; a1+=As[iw+4][jj]*vv;
            a2+=As[iw+8][jj]*vv; a3+=As[iw+12][jj]*vv;
        }
        __syncthreads();
    }
    if (n<32){
        g_feat[(i0+iw)   *FEAT + h*32+n]=a0;
        g_feat[(i0+iw+4) *FEAT + h*32+n]=a1;
        g_feat[(i0+iw+8) *FEAT + h*32+n]=a2;
        g_feat[(i0+iw+12)*FEAT + h*32+n]=a3;
    } else if (n<56){
        int c=n-32;
        g_ptg[(i0+iw)   *192 + h*24+c]=a0;
        g_ptg[(i0+iw+4) *192 + h*24+c]=a1;
        g_ptg[(i0+iw+8) *192 + h*24+c]=a2;
        g_ptg[(i0+iw+12)*192 + h*24+c]=a3;
    }
}

// ---- pair_out ----
__global__ __launch_bounds__(256) void k_pair_out(const float* __restrict__ attn){
    int i=blockIdx.x, tid=threadIdx.x;
    int o=tid&31, jw=tid>>5, h=o>>2;
    float acc=0.f;
    for(int j=jw;j<LL;j+=8)
        acc += attn[((long)h*LL+i)*LL+j]*g_pv[((long)i*LL+j)*32+o];
    __shared__ float red[8][32];
    red[jw][o]=acc;
    __syncthreads();
    if(tid<32){
        float s=0; for(int w=0;w<8;w++)s+=red[w][tid];
        g_feat[i*FEAT+512+tid]=s;
    }
}

// ---- back to local frame + norms ----
__global__ __launch_bounds__(64) void k_local(const float* __restrict__ R,
                                              const float* __restrict__ t){
    int i=blockIdx.x, tid=threadIdx.x;
    __shared__ float Rl[9], tl[3];
    if(tid<9) Rl[tid]=R[i*9+tid];
    if(tid<3) tl[tid]=t[i*3+tid];
    __syncthreads();
    float gx=g_ptg[i*192+tid*3]  -tl[0];
    float gy=g_ptg[i*192+tid*3+1]-tl[1];
    float gz=g_ptg[i*192+tid*3+2]-tl[2];
    float lx=Rl[0]*gx+Rl[3]*gy+Rl[6]*gz;
    float ly=Rl[1]*gx+Rl[4]*gy+Rl[7]*gz;
    float lz=Rl[2]*gx+Rl[5]*gy+Rl[8]*gz;
    g_feat[i*FEAT+256+tid*3]  =lx;
    g_feat[i*FEAT+256+tid*3+1]=ly;
    g_feat[i*FEAT+256+tid*3+2]=lz;
    g_feat[i*FEAT+448+tid]=sqrtf(lx*lx+ly*ly+lz*lz+1e-8f);
}

extern "C" void kernel_launch(void* const* d_in, const int* in_sizes, int n_in,
                              void* d_out, int out_size){
    const float* s      =(const float*)d_in[0];
    const float* z      =(const float*)d_in[1];
    const float* R      =(const float*)d_in[2];
    const float* t      =(const float*)d_in[3];
    const float* mask   =(const float*)d_in[4];
    const float* ln_s_w =(const float*)d_in[5];
    const float* ln_s_b =(const float*)d_in[6];
    const float* ln_z_w =(const float*)d_in[7];
    const float* ln_z_b =(const float*)d_in[8];
    const float* Wq     =(const float*)d_in[9];
    const float* Wk     =(const float*)d_in[10];
    const float* Wv     =(const float*)d_in[11];
    const float* Wpb    =(const float*)d_in[12];
    const float* Wq_pts =(const float*)d_in[13];
    const float* Wk_pts =(const float*)d_in[14];
    const float* Wv_pts =(const float*)d_in[15];
    const float* pw     =(const float*)d_in[16];
    const float* Wpo    =(const float*)d_in[17];
    const float* W_out  =(const float*)d_in[18];
    const float* b_out  =(const float*)d_in[19];
    float* out  = (float*)d_out;
    float* attn = out + ATTN_OFF;

    float *p_sln,*p_wcat,*p_proj,*p_vpg,*p_feat;
    cudaGetSymbolAddress((void**)&p_sln,  g_sln);
    cudaGetSymbolAddress((void**)&p_wcat, g_Wcat);
    cudaGetSymbolAddress((void**)&p_proj, g_proj);
    cudaGetSymbolAddress((void**)&p_vpg,  g_vpg);
    cudaGetSymbolAddress((void**)&p_feat, g_feat);

    static cudaStream_t sB = nullptr;
    static cudaEvent_t evF1=nullptr, evJ1=nullptr, evF2=nullptr, evJ2=nullptr;
    if (sB == nullptr){
        cudaStreamCreateWithFlags(&sB, cudaStreamNonBlocking);
        cudaEventCreateWithFlags(&evF1, cudaEventDisableTiming);
        cudaEventCreateWithFlags(&evJ1, cudaEventDisableTiming);
        cudaEventCreateWithFlags(&evF2, cudaEventDisableTiming);
        cudaEventCreateWithFlags(&evJ2, cudaEventDisableTiming);
    }

    // fork 1: projection chain (sB) || z pass (s0)
    cudaEventRecord(evF1, 0);
    cudaStreamWaitEvent(sB, evF1, 0);

    k_ln_s<<<LL,256,0,sB>>>(s, ln_s_w, ln_s_b);
    k_wcat<<<(CS*NPROJ)/256,256,0,sB>>>(Wq, Wk, Wv, Wq_pts, Wk_pts, Wv_pts);
    k_sgemm2<<<dim3(NPROJ/64, LL/64),256,0,sB>>>(p_sln, p_wcat, nullptr, nullptr, p_proj, LL, NPROJ, CS);
    k_transpose_k<<<dim3(8,24),256,0,sB>>>();
    k_transform<<<LL,128,0,sB>>>(R, t);
    cudaEventRecord(evJ1, sB);

    k_premix<<<11,256>>>(ln_z_w, ln_z_b, Wpb, Wpo);
    k_zpass<<<(LL*LL)/256,256>>>(z);

    cudaStreamWaitEvent(0, evJ1, 0);
    k_logits_softmax<<<dim3(LL/4,NH),256>>>(mask, pw, attn);

    // fork 2: attn_fused + local (sB) || pair_out (s0)
    cudaEventRecord(evF2, 0);
    cudaStreamWaitEvent(sB, evF2, 0);
    k_attn_fused<<<dim3(LL/16,NH),256,0,sB>>>(attn, p_proj + OFF_V, p_vpg);
    k_local<<<LL,64,0,sB>>>(R, t);
    cudaEventRecord(evJ2, sB);

    k_pair_out<<<LL,256>>>(attn);

    cudaStreamWaitEvent(0, evJ2, 0);
    k_sgemm2<<<dim3(CS/64, LL/64),256>>>(p_feat, W_out, b_out, mask, out, LL, CS, FEAT);
}

// round 12
// speedup vs baseline: 1.0898x; 1.0058x over previous
#include <cuda_runtime.h>
#include <math.h>

#define LL 768
#define CS 256
#define CZ 128
#define NH 8
#define FEAT 544
#define NPROJ 1152
#define ATTN_OFF (LL*CS)

#define OFF_Q   0
#define OFF_K   256
#define OFF_V   512
#define OFF_QPL 768
#define OFF_KPL 864
#define OFF_VPL 960

typedef unsigned long long ull;

__device__ float g_sln[LL*CS];
__device__ float g_Wcat[CS*NPROJ];
__device__ float g_proj[LL*NPROJ];
__device__ float g_kt[CS*LL];            // [c][j]
__device__ float g_qpg[LL*96];           // [i][h*12+pp]
__device__ float g_kpgt[96*LL];          // [(h*12+pp)][j]
__device__ float g_vpg[LL*192];          // [j][h*24+pp]
__device__ float g_qn[LL*NH];
__device__ float g_knt[NH*LL];
__device__ float g_pb[(long)NH*LL*LL];   // [h][i][j]
__device__ float g_pv[(long)LL*LL*32];   // [pair][h*4+d]
__device__ float g_feat[LL*FEAT];
__device__ float g_ptg[LL*192];
__device__ float g_T1[40];
__device__ float g_T0[40];
__device__ ull g_Wz2[CZ*40];             // lnw-folded, (w,w)-DUPLICATED weights, one ull per col

__device__ __forceinline__ ull pk2(float lo, float hi){
    ull r; asm("mov.b64 %0,{%1,%2};":"=l"(r):"f"(lo),"f"(hi)); return r;
}
__device__ __forceinline__ void fma2(ull &d, ull a, ull b){
    asm("fma.rn.f32x2 %0, %1, %2, %0;" : "+l"(d) : "l"(a), "l"(b));
}
__device__ __forceinline__ float2 upk2(ull v){
    float2 r; asm("mov.b64 {%0,%1},%2;":"=f"(r.x),"=f"(r.y):"l"(v)); return r;
}

// ---- LN of s ----
__global__ __launch_bounds__(256) void k_ln_s(const float* __restrict__ s,
                                              const float* __restrict__ w,
                                              const float* __restrict__ b){
    int i = blockIdx.x, t = threadIdx.x;
    float x = s[i*CS + t];
    __shared__ float sh[8]; __shared__ float s_m, s_r;
    float v = x;
    #pragma unroll
    for (int o=16;o;o>>=1) v += __shfl_xor_sync(~0u,v,o);
    if ((t&31)==0) sh[t>>5]=v;
    __syncthreads();
    if (t==0){ float u=0; for(int kk=0;kk<8;kk++)u+=sh[kk]; s_m=u*(1.f/256.f); }
    __syncthreads();
    float d = x - s_m; v = d*d;
    #pragma unroll
    for (int o=16;o;o>>=1) v += __shfl_xor_sync(~0u,v,o);
    if ((t&31)==0) sh[t>>5]=v;
    __syncthreads();
    if (t==0){ float u=0; for(int kk=0;kk<8;kk++)u+=sh[kk]; s_r=rsqrtf(u*(1.f/256.f)+1e-5f); }
    __syncthreads();
    g_sln[i*CS+t] = d*s_r*w[t] + b[t];
}

// ---- premix: duplicated (w,w) weight table + T1/T0 fold constants ----
__global__ void k_premix(const float* __restrict__ lnw, const float* __restrict__ lnb,
                         const float* __restrict__ Wpb, const float* __restrict__ Wpo){
    int idx = blockIdx.x*256 + threadIdx.x;
    if (idx < 5120){
        int c = idx/40, n = idx%40;
        float w = lnw[c]*((n<8)?Wpb[c*8+n]:Wpo[c*32+n-8]);
        g_Wz2[idx] = pk2(w,w);
    } else if (idx < 5160){
        int n = idx-5120;
        float t1=0.f, t0=0.f;
        for(int c=0;c<CZ;c++){
            float wv = (n<8)?Wpb[c*8+n]:Wpo[c*32+n-8];
            t1 += lnw[c]*wv; t0 += lnb[c]*wv;
        }
        g_T1[n]=t1; g_T0[n]=t0;
    }
}

// ---- concat projection weights ----
__global__ __launch_bounds__(256) void k_wcat(const float* __restrict__ Wq, const float* __restrict__ Wk,
                                              const float* __restrict__ Wv, const float* __restrict__ Wqp,
                                              const float* __restrict__ Wkp, const float* __restrict__ Wvp){
    int idx = blockIdx.x*256 + threadIdx.x;
    int k = idx/NPROJ, n = idx%NPROJ;
    float v;
    if      (n < 256)  v = Wq [k*256 + n];
    else if (n < 512)  v = Wk [k*256 + n-256];
    else if (n < 768)  v = Wv [k*256 + n-512];
    else if (n < 864)  v = Wqp[k*96  + n-768];
    else if (n < 960)  v = Wkp[k*96  + n-864];
    else               v = Wvp[k*192 + n-960];
    g_Wcat[idx] = v;
}

// ---- SGEMM ----
__global__ __launch_bounds__(256) void k_sgemm2(const float* __restrict__ A,
                                                const float* __restrict__ W,
                                                const float* __restrict__ bias,
                                                const float* __restrict__ msk,
                                                float* __restrict__ C,
                                                int M, int N, int K){
    __shared__ float As[16][68], Bs[16][68];
    int tid = threadIdx.x;
    int tx = tid&15, ty = tid>>4;
    const float* Ab = A + (long)(blockIdx.y*64)*K;
    const float* Wb = W + blockIdx.x*64;
    float acc[4][4];
    #pragma unroll
    for(int u=0;u<4;u++)
        #pragma unroll
        for(int w2=0;w2<4;w2++) acc[u][w2]=0.f;

    int ar = tid>>2, ak = (tid&3)*4;
    int bk = tid>>4, bn = (tid&15)*4;
    float4 a4 = *(const float4*)&Ab[ar*K + ak];
    float4 b4 = *(const float4*)&Wb[(long)bk*N + bn];

    for(int k0=0;k0<K;k0+=16){
        As[ak+0][ar]=a4.x; As[ak+1][ar]=a4.y; As[ak+2][ar]=a4.z; As[ak+3][ar]=a4.w;
        *(float4*)&Bs[bk][bn]=b4;
        __syncthreads();
        if (k0+16 < K){
            a4 = *(const float4*)&Ab[ar*K + k0+16 + ak];
            b4 = *(const float4*)&Wb[(long)(k0+16+bk)*N + bn];
        }
        #pragma unroll
        for(int kk=0;kk<16;kk++){
            float4 av=*(const float4*)&As[kk][ty*4];
            float4 bv=*(const float4*)&Bs[kk][tx*4];
            float aa[4]={av.x,av.y,av.z,av.w};
            float bb[4]={bv.x,bv.y,bv.z,bv.w};
            #pragma unroll
            for(int u=0;u<4;u++)
                #pragma unroll
                for(int w2=0;w2<4;w2++) acc[u][w2] += aa[u]*bb[w2];
        }
        __syncthreads();
    }
    int gm0 = blockIdx.y*64 + ty*4, gn0 = blockIdx.x*64 + tx*4;
    #pragma unroll
    for(int u=0;u<4;u++){
        int gm = gm0+u;
        float mv = msk ? msk[gm] : 1.f;
        #pragma unroll
        for(int w2=0;w2<4;w2++){
            int gn = gn0+w2;
            float vv = acc[u][w2];
            if (bias) vv += bias[gn];
            C[(long)gm*N+gn] = vv*mv;
        }
    }
}

// ---- transpose k ----
__global__ __launch_bounds__(256) void k_transpose_k(){
    __shared__ float tile[32][33];
    int c0=blockIdx.x*32, j0=blockIdx.y*32;
    int tx=threadIdx.x&31, ty=threadIdx.x>>5;
    for(int r=ty;r<32;r+=8) tile[r][tx]=g_proj[(j0+r)*NPROJ + OFF_K + c0+tx];
    __syncthreads();
    for(int r=ty;r<32;r+=8) g_kt[(c0+r)*LL+j0+tx]=tile[tx][r];
}

// ---- rigid transform ----
__global__ __launch_bounds__(128) void k_transform(const float* __restrict__ R,
                                                   const float* __restrict__ t){
    int i=blockIdx.x, tid=threadIdx.x;
    __shared__ float Rl[9], tl[3];
    if(tid<9) Rl[tid]=R[i*9+tid];
    if(tid<3) tl[tid]=t[i*3+tid];
    __syncthreads();
    if (tid<32){
        const float* src = g_proj + i*NPROJ + OFF_QPL + tid*3;
        float p0=src[0], p1=src[1], p2=src[2];
        float gx=Rl[0]*p0+Rl[1]*p1+Rl[2]*p2+tl[0];
        float gy=Rl[3]*p0+Rl[4]*p1+Rl[5]*p2+tl[1];
        float gz=Rl[6]*p0+Rl[7]*p1+Rl[8]*p2+tl[2];
        g_qpg[i*96+tid*3]=gx; g_qpg[i*96+tid*3+1]=gy; g_qpg[i*96+tid*3+2]=gz;
        float sq=gx*gx+gy*gy+gz*gz;
        sq += __shfl_xor_sync(~0u,sq,1); sq += __shfl_xor_sync(~0u,sq,2);
        if((tid&3)==0) g_qn[i*NH+(tid>>2)]=sq;
    } else if (tid<64){
        int idx=tid-32;
        const float* src = g_proj + i*NPROJ + OFF_KPL + idx*3;
        float p0=src[0], p1=src[1], p2=src[2];
        float gx=Rl[0]*p0+Rl[1]*p1+Rl[2]*p2+tl[0];
        float gy=Rl[3]*p0+Rl[4]*p1+Rl[5]*p2+tl[1];
        float gz=Rl[6]*p0+Rl[7]*p1+Rl[8]*p2+tl[2];
        g_kpgt[(idx*3+0)*LL+i]=gx; g_kpgt[(idx*3+1)*LL+i]=gy; g_kpgt[(idx*3+2)*LL+i]=gz;
        float sq=gx*gx+gy*gy+gz*gz;
        sq += __shfl_xor_sync(~0u,sq,1); sq += __shfl_xor_sync(~0u,sq,2);
        if((idx&3)==0) g_knt[(idx>>2)*LL+i]=sq;
    } else {
        int idx=tid-64;
        const float* src = g_proj + i*NPROJ + OFF_VPL + idx*3;
        float p0=src[0], p1=src[1], p2=src[2];
        g_vpg[i*192+idx*3+0]=Rl[0]*p0+Rl[1]*p1+Rl[2]*p2+tl[0];
        g_vpg[i*192+idx*3+1]=Rl[3]*p0+Rl[4]*p1+Rl[5]*p2+tl[1];
        g_vpg[i*192+idx*3+2]=Rl[6]*p0+Rl[7]*p1+Rl[8]*p2+tl[2];
    }
}

// ---- z pass: LN folded, z read once -> pair_bias + pair_v
//      row-paired f32x2 accumulators: z pre-packed by layout, weights pre-duplicated ----
__global__ __launch_bounds__(256) void k_zpass(const float* __restrict__ z){
    __shared__ __align__(16) float U[256*41];       // union: Zs[16][264] then Os[256][41]
    __shared__ __align__(16) ull Wd[16][40];
    __shared__ float s_mean[256], s_rstd[256], T1s[40], T0s[40];
    float* Zs = U;
    float (*Os)[41] = (float(*)[41])U;
    int tid=threadIdx.x;
    long pair0=(long)blockIdx.x*256;
    if(tid<40){ T1s[tid]=g_T1[tid]; T0s[tid]=g_T0[tid]; }

    int rbase = (tid&63)*4;      // rows rbase..rbase+3 (2 packed pairs)
    int ty = tid>>6;             // cols ty*10..ty*10+9
    ull acc2[2][10];             // [row-pair][col]
    #pragma unroll
    for(int g=0;g<2;g++)
        #pragma unroll
        for(int n=0;n<10;n++) acc2[g][n]=0ull;

    int rq=tid>>2, kq=tid&3;
    float sums[4]={0,0,0,0}, sqs[4]={0,0,0,0};
    float4 pf[4];
    #pragma unroll
    for(int i=0;i<4;i++) pf[i]=*(const float4*)&z[(pair0+rq+64*i)*CZ + kq*4];

    for(int k0=0;k0<CZ;k0+=16){
        #pragma unroll
        for(int i=0;i<4;i++){
            float4 v=pf[i];
            sums[i]+=v.x+v.y+v.z+v.w;
            sqs[i]+=v.x*v.x+v.y*v.y+v.z*v.z+v.w*v.w;
            int row=rq+64*i, kkb=kq*4;
            Zs[(kkb+0)*264 + (row ^ (((kkb+0)&7)<<2))]=v.x;
            Zs[(kkb+1)*264 + (row ^ (((kkb+1)&7)<<2))]=v.y;
            Zs[(kkb+2)*264 + (row ^ (((kkb+2)&7)<<2))]=v.z;
            Zs[(kkb+3)*264 + (row ^ (((kkb+3)&7)<<2))]=v.w;
        }
        // stage 16x40 duplicated weights
        for(int l=tid;l<640;l+=256){
            int kk=l/40, c=l%40;
            Wd[kk][c]=g_Wz2[(k0+kk)*40+c];
        }
        __syncthreads();
        if(k0+16<CZ){
            #pragma unroll
            for(int i=0;i<4;i++) pf[i]=*(const float4*)&z[(pair0+rq+64*i)*CZ + k0+16 + kq*4];
        }
        #pragma unroll
        for(int kk=0;kk<16;kk++){
            // rows rbase..rbase+3: two aligned f32x2 pairs, no packing needed
            ulonglong2 zz=*(const ulonglong2*)&Zs[kk*264 + (rbase ^ ((kk&7)<<2))];
            const ull* wrow=&Wd[kk][ty*10];
            ulonglong2 w0=*(const ulonglong2*)(wrow+0);
            ulonglong2 w1=*(const ulonglong2*)(wrow+2);
            ulonglong2 w2=*(const ulonglong2*)(wrow+4);
            ulonglong2 w3=*(const ulonglong2*)(wrow+6);
            ulonglong2 w4=*(const ulonglong2*)(wrow+8);
            ull wv[10]={w0.x,w0.y,w1.x,w1.y,w2.x,w2.y,w3.x,w3.y,w4.x,w4.y};
            #pragma unroll
            for(int nn=0;nn<10;nn++){
                fma2(acc2[0][nn],zz.x,wv[nn]);
                fma2(acc2[1][nn],zz.y,wv[nn]);
            }
        }
        __syncthreads();
    }
    #pragma unroll
    for(int i=0;i<4;i++){
        sums[i]+=__shfl_xor_sync(~0u,sums[i],1); sums[i]+=__shfl_xor_sync(~0u,sums[i],2);
        sqs[i] +=__shfl_xor_sync(~0u,sqs[i],1);  sqs[i] +=__shfl_xor_sync(~0u,sqs[i],2);
    }
    if(kq==0){
        #pragma unroll
        for(int i=0;i<4;i++){
            float m=sums[i]*(1.f/128.f);
            s_mean[rq+64*i]=m;
            s_rstd[rq+64*i]=rsqrtf(sqs[i]*(1.f/128.f)-m*m+1e-5f);
        }
    }
    __syncthreads();
    #pragma unroll
    for(int g=0;g<2;g++){
        int r0=rbase+2*g, r1=r0+1;
        float rs0=s_rstd[r0], mn0=s_mean[r0];
        float rs1=s_rstd[r1], mn1=s_mean[r1];
        #pragma unroll
        for(int nn=0;nn<10;nn++){
            float2 a=upk2(acc2[g][nn]);
            int n=ty*10+nn;
            Os[r0][n]=rs0*(a.x-mn0*T1s[n])+T0s[n];
            Os[r1][n]=rs1*(a.y-mn1*T1s[n])+T0s[n];
        }
    }
    __syncthreads();
    for(int l=tid;l<2048;l+=256){
        int hh=l>>8, r=l&255;
        long p=pair0+r; int i=(int)(p/LL), j=(int)(p%LL);
        g_pb[((long)hh*LL+i)*LL+j]=Os[r][hh];
    }
    for(int l=tid;l<8192;l+=256){
        int r=l>>5, o=l&31;
        g_pv[(pair0+r)*32+o]=Os[r][8+o];
    }
}

// ---- fused logits + softmax -> attn ----
__global__ __launch_bounds__(256) void k_logits_softmax(const float* __restrict__ mask,
                                                        const float* __restrict__ pweights,
                                                        float* __restrict__ attn){
    int h=blockIdx.y, i0=blockIdx.x*4, tid=threadIdx.x;
    __shared__ float qv[4][32], qp[4][12], qnv[4], mi[4], red[8][4], bmax[4], brcp[4], s_pw;
    if(tid<128){ int ii=tid>>5, c=tid&31; qv[ii][c]=g_proj[(i0+ii)*NPROJ + OFF_Q + h*32+c]; }
    else if(tid<176){ int l=tid-128, ii=l/12, pp=l%12; qp[ii][pp]=g_qpg[(i0+ii)*96+h*12+pp]; }
    else if(tid<180){ int ii=tid-176; qnv[ii]=g_qn[(i0+ii)*NH+h]; mi[ii]=mask[i0+ii]; }
    else if(tid==180){ float xw=pweights[h]; s_pw=0.5f*log1pf(expf(xw)); }
    __syncthreads();

    float lv[3][4];
    const float invs = 0.17677669529663687f;
    #pragma unroll
    for(int jj=0;jj<3;jj++){
        int j=jj*256+tid;
        float sl[4]={0,0,0,0};
        const float* kt = g_kt + h*32*LL + j;
        #pragma unroll
        for(int c=0;c<32;c++){
            float kc=kt[c*LL];
            sl[0]+=qv[0][c]*kc; sl[1]+=qv[1][c]*kc; sl[2]+=qv[2][c]*kc; sl[3]+=qv[3][c]*kc;
        }
        float pd[4]={0,0,0,0};
        const float* kp = g_kpgt + h*12*LL + j;
        #pragma unroll
        for(int pp=0;pp<12;pp++){
            float kc=kp[pp*LL];
            pd[0]+=qp[0][pp]*kc; pd[1]+=qp[1][pp]*kc; pd[2]+=qp[2][pp]*kc; pd[3]+=qp[3][pp]*kc;
        }
        float knj=g_knt[h*LL+j], mj=mask[j];
        const float* pbp = g_pb + ((long)h*LL+i0)*LL + j;
        #pragma unroll
        for(int ii=0;ii<4;ii++){
            float lg = sl[ii]*invs + pbp[(long)ii*LL] - s_pw*(qnv[ii]+knj-2.f*pd[ii]);
            if (mi[ii]*mj==0.f) lg=-1e9f;
            lv[jj][ii]=lg;
        }
    }
    #pragma unroll
    for(int ii=0;ii<4;ii++){
        float m=fmaxf(fmaxf(lv[0][ii],lv[1][ii]),lv[2][ii]);
        #pragma unroll
        for(int o=16;o;o>>=1) m=fmaxf(m,__shfl_xor_sync(~0u,m,o));
        if((tid&31)==0) red[tid>>5][ii]=m;
    }
    __syncthreads();
    if(tid<4){ float m=red[0][tid]; for(int w=1;w<8;w++)m=fmaxf(m,red[w][tid]); bmax[tid]=m; }
    __syncthreads();
    float ev[3][4], sm[4]={0,0,0,0};
    #pragma unroll
    for(int jj=0;jj<3;jj++)
        #pragma unroll
        for(int ii=0;ii<4;ii++){ float e=__expf(lv[jj][ii]-bmax[ii]); ev[jj][ii]=e; sm[ii]+=e; }
    __syncthreads();
    #pragma unroll
    for(int ii=0;ii<4;ii++){
        float s=sm[ii];
        #pragma unroll
        for(int o=16;o;o>>=1) s+=__shfl_xor_sync(~0u,s,o);
        if((tid&31)==0) red[tid>>5][ii]=s;
    }
    __syncthreads();
    if(tid<4){ float s=0; for(int w=0;w<8;w++)s+=red[w][tid]; brcp[tid]=1.f/s; }
    __syncthreads();
    #pragma unroll
    for(int jj=0;jj<3;jj++){
        int j=jj*256+tid;
        #pragma unroll
        for(int ii=0;ii<4;ii++)
            attn[((long)h*LL+i0+ii)*LL+j]=ev[jj][ii]*brcp[ii];
    }
}

// ---- fused attn @ [V | v_pts_global] ----
__global__ __launch_bounds__(256) void k_attn_fused(const float* __restrict__ attn,
                                                    const float* __restrict__ V1,
                                                    const float* __restrict__ V2){
    int h=blockIdx.y, i0=blockIdx.x*16, tid=threadIdx.x;
    __shared__ float As[16][33], Vs[32][64];
    int n=tid&63, iw=tid>>6;
    float a0=0.f,a1=0.f,a2=0.f,a3=0.f;
    for(int j0=0;j0<LL;j0+=32){
        for(int l=tid;l<512;l+=256){
            int r=l>>5, jj=l&31;
            As[r][jj]=attn[((long)h*LL+i0+r)*LL+j0+jj];
        }
        for(int l=tid;l<2048;l+=256){
            int r=l>>6, c=l&63;
            float v;
            if (c<32)      v = V1[(long)(j0+r)*NPROJ + h*32 + c];
            else if (c<56) v = V2[(long)(j0+r)*192   + h*24 + (c-32)];
            else           v = 0.f;
            Vs[r][c]=v;
        }
        __syncthreads();
        #pragma unroll
        for(int jj=0;jj<32;jj++){
            float vv=Vs[jj][n];
            a0+=As[iw][jj]*vv; a1+=As[iw+4][jj]*vv;
            a2+=As[iw+8][jj]*vv; a3+=As[iw+12][jj]*vv;
        }
        __syncthreads();
    }
    if (n<32){
        g_feat[(i0+iw)   *FEAT + h*32+n]=a0;
        g_feat[(i0+iw+4) *FEAT + h*32+n]=a1;
        g_feat[(i0+iw+8) *FEAT + h*32+n]=a2;
        g_feat[(i0+iw+12)*FEAT + h*32+n]=a3;
    } else if (n<56){
        int c=n-32;
        g_ptg[(i0+iw)   *192 + h*24+c]=a0;
        g_ptg[(i0+iw+4) *192 + h*24+c]=a1;
        g_ptg[(i0+iw+8) *192 + h*24+c]=a2;
        g_ptg[(i0+iw+12)*192 + h*24+c]=a3;
    }
}

// ---- pair_out ----
__global__ __launch_bounds__(256) void k_pair_out(const float* __restrict__ attn){
    int i=blockIdx.x, tid=threadIdx.x;
    int o=tid&31, jw=tid>>5, h=o>>2;
    float acc=0.f;
    for(int j=jw;j<LL;j+=8)
        acc += attn[((long)h*LL+i)*LL+j]*g_pv[((long)i*LL+j)*32+o];
    __shared__ float red[8][32];
    red[jw][o]=acc;
    __syncthreads();
    if(tid<32){
        float s=0; for(int w=0;w<8;w++)s+=red[w][tid];
        g_feat[i*FEAT+512+tid]=s;
    }
}

// ---- back to local frame + norms ----
__global__ __launch_bounds__(64) void k_local(const float* __restrict__ R,
                                              const float* __restrict__ t){
    int i=blockIdx.x, tid=threadIdx.x;
    __shared__ float Rl[9], tl[3];
    if(tid<9) Rl[tid]=R[i*9+tid];
    if(tid<3) tl[tid]=t[i*3+tid];
    __syncthreads();
    float gx=g_ptg[i*192+tid*3]  -tl[0];
    float gy=g_ptg[i*192+tid*3+1]-tl[1];
    float gz=g_ptg[i*192+tid*3+2]-tl[2];
    float lx=Rl[0]*gx+Rl[3]*gy+Rl[6]*gz;
    float ly=Rl[1]*gx+Rl[4]*gy+Rl[7]*gz;
    float lz=Rl[2]*gx+Rl[5]*gy+Rl[8]*gz;
    g_feat[i*FEAT+256+tid*3]  =lx;
    g_feat[i*FEAT+256+tid*3+1]=ly;
    g_feat[i*FEAT+256+tid*3+2]=lz;
    g_feat[i*FEAT+448+tid]=sqrtf(lx*lx+ly*ly+lz*lz+1e-8f);
}

extern "C" void kernel_launch(void* const* d_in, const int* in_sizes, int n_in,
                              void* d_out, int out_size){
    const float* s      =(const float*)d_in[0];
    const float* z      =(const float*)d_in[1];
    const float* R      =(const float*)d_in[2];
    const float* t      =(const float*)d_in[3];
    const float* mask   =(const float*)d_in[4];
    const float* ln_s_w =(const float*)d_in[5];
    const float* ln_s_b =(const float*)d_in[6];
    const float* ln_z_w =(const float*)d_in[7];
    const float* ln_z_b =(const float*)d_in[8];
    const float* Wq     =(const float*)d_in[9];
    const float* Wk     =(const float*)d_in[10];
    const float* Wv     =(const float*)d_in[11];
    const float* Wpb    =(const float*)d_in[12];
    const float* Wq_pts =(const float*)d_in[13];
    const float* Wk_pts =(const float*)d_in[14];
    const float* Wv_pts =(const float*)d_in[15];
    const float* pw     =(const float*)d_in[16];
    const float* Wpo    =(const float*)d_in[17];
    const float* W_out  =(const float*)d_in[18];
    const float* b_out  =(const float*)d_in[19];
    float* out  = (float*)d_out;
    float* attn = out + ATTN_OFF;

    float *p_sln,*p_wcat,*p_proj,*p_vpg,*p_feat;
    cudaGetSymbolAddress((void**)&p_sln,  g_sln);
    cudaGetSymbolAddress((void**)&p_wcat, g_Wcat);
    cudaGetSymbolAddress((void**)&p_proj, g_proj);
    cudaGetSymbolAddress((void**)&p_vpg,  g_vpg);
    cudaGetSymbolAddress((void**)&p_feat, g_feat);

    static cudaStream_t sB = nullptr;
    static cudaEvent_t evF1=nullptr, evJ1=nullptr;
    if (sB == nullptr){
        cudaStreamCreateWithFlags(&sB, cudaStreamNonBlocking);
        cudaEventCreateWithFlags(&evF1, cudaEventDisableTiming);
        cudaEventCreateWithFlags(&evJ1, cudaEventDisableTiming);
    }

    // fork 1: projection chain (sB) || z pass (s0)  — R7 schedule exactly
    cudaEventRecord(evF1, 0);
    cudaStreamWaitEvent(sB, evF1, 0);

    k_ln_s<<<LL,256,0,sB>>>(s, ln_s_w, ln_s_b);
    k_wcat<<<(CS*NPROJ)/256,256,0,sB>>>(Wq, Wk, Wv, Wq_pts, Wk_pts, Wv_pts);
    k_sgemm2<<<dim3(NPROJ/64, LL/64),256,0,sB>>>(p_sln, p_wcat, nullptr, nullptr, p_proj, LL, NPROJ, CS);
    k_transpose_k<<<dim3(8,24),256,0,sB>>>();
    k_transform<<<LL,128,0,sB>>>(R, t);
    cudaEventRecord(evJ1, sB);

    k_premix<<<21,256>>>(ln_z_w, ln_z_b, Wpb, Wpo);
    k_zpass<<<(LL*LL)/256,256>>>(z);

    cudaStreamWaitEvent(0, evJ1, 0);
    k_logits_softmax<<<dim3(LL/4,NH),256>>>(mask, pw, attn);
    k_attn_fused<<<dim3(LL/16,NH),256>>>(attn, p_proj + OFF_V, p_vpg);
    k_pair_out<<<LL,256>>>(attn);
    k_local<<<LL,64>>>(R, t);
    k_sgemm2<<<dim3(CS/64, LL/64),256>>>(p_feat, W_out, b_out, mask, out, LL, CS, FEAT);
}

// round 15
// speedup vs baseline: 1.3099x; 1.2020x over previous
#include <cuda_runtime.h>
#include <cuda_bf16.h>
#include <cstdint>
#include <stdint.h>
#include <math.h>

#define LL 768
#define CS 256
#define CZ 128
#define NH 8
#define FEAT 544
#define NPROJ 1152
#define ATTN_OFF (LL*CS)

#define OFF_Q   0
#define OFF_K   256
#define OFF_V   512
#define OFF_QPL 768
#define OFF_KPL 864
#define OFF_VPL 960

typedef unsigned long long ull;

__device__ float g_sln[LL*CS];
__device__ float g_Wcat[CS*NPROJ];
__device__ float g_proj[LL*NPROJ];
__device__ float g_kt[CS*LL];
__device__ float g_qpg[LL*96];
__device__ float g_kpgt[96*LL];
__device__ float g_vpg[LL*192];
__device__ float g_qn[LL*NH];
__device__ float g_knt[NH*LL];
__device__ float g_pb[(long)NH*LL*LL];
__device__ float g_pv[(long)LL*LL*32];
__device__ float g_feat[LL*FEAT];
__device__ float g_ptg[LL*192];
__device__ float g_T1[40];
__device__ float g_T0[40];
__device__ unsigned g_Bfrag[5120];      // [hi:0..2559 | lo:2560..5119] B fragments

// ---------------- zpass_mma smem layout (bytes) ----------------
#define ZROWS 128
#define OFF_AH  0
#define OFF_AL  33792
#define OFF_BF  67584
#define OFF_BFL 77824
#define OFF_SUM 88064
#define OFF_SQ  88576
#define OFF_T1S 89088
#define OFF_T0S 89248
#define SMEM_Z  89408

__device__ __forceinline__ void mma16816(float* d, const unsigned* a, const unsigned* b){
    asm volatile("mma.sync.aligned.m16n8k16.row.col.f32.bf16.bf16.f32 "
        "{%0,%1,%2,%3}, {%4,%5,%6,%7}, {%8,%9}, {%0,%1,%2,%3};"
        : "+f"(d[0]),"+f"(d[1]),"+f"(d[2]),"+f"(d[3])
        : "r"(a[0]),"r"(a[1]),"r"(a[2]),"r"(a[3]), "r"(b[0]),"r"(b[1]));
}
__device__ __forceinline__ unsigned pkbf(float x, float y){
    __nv_bfloat162 h = __floats2bfloat162_rn(x, y);
    return *(unsigned*)&h;
}

// ---- LN of s ----
__global__ __launch_bounds__(256) void k_ln_s(const float* __restrict__ s,
                                              const float* __restrict__ w,
                                              const float* __restrict__ b){
    int i = blockIdx.x, t = threadIdx.x;
    float x = s[i*CS + t];
    __shared__ float sh[8]; __shared__ float s_m, s_r;
    float v = x;
    #pragma unroll
    for (int o=16;o;o>>=1) v += __shfl_xor_sync(~0u,v,o);
    if ((t&31)==0) sh[t>>5]=v;
    __syncthreads();
    if (t==0){ float u=0; for(int kk=0;kk<8;kk++)u+=sh[kk]; s_m=u*(1.f/256.f); }
    __syncthreads();
    float d = x - s_m; v = d*d;
    #pragma unroll
    for (int o=16;o;o>>=1) v += __shfl_xor_sync(~0u,v,o);
    if ((t&31)==0) sh[t>>5]=v;
    __syncthreads();
    if (t==0){ float u=0; for(int kk=0;kk<8;kk++)u+=sh[kk]; s_r=rsqrtf(u*(1.f/256.f)+1e-5f); }
    __syncthreads();
    g_sln[i*CS+t] = d*s_r*w[t] + b[t];
}

// ---- premix: B fragment table (bf16 split) + T1/T0 ----
__global__ void k_premix(const float* __restrict__ lnw, const float* __restrict__ lnb,
                         const float* __restrict__ Wpb, const float* __restrict__ Wpo){
    int idx = blockIdx.x*256 + threadIdx.x;
    if (idx < 2560){
        int breg = idx & 1;
        int r    = idx >> 1;
        int lane = r & 31;
        int q    = r >> 5;
        int nt   = q % 5;
        int kt   = q / 5;
        int g  = lane >> 2, t4 = lane & 3;
        int k  = kt*16 + t4*2 + breg*8;
        int n  = nt*8 + g;
        float w0 = lnw[k]  *((n<8)?Wpb[k*8+n]    :Wpo[k*32+n-8]);
        float w1 = lnw[k+1]*((n<8)?Wpb[(k+1)*8+n]:Wpo[(k+1)*32+n-8]);
        __nv_bfloat16 h0 = __float2bfloat16(w0), h1 = __float2bfloat16(w1);
        float l0 = w0 - __bfloat162float(h0), l1 = w1 - __bfloat162float(h1);
        g_Bfrag[idx]        = pkbf(__bfloat162float(h0), __bfloat162float(h1));
        g_Bfrag[2560 + idx] = pkbf(l0, l1);
    } else if (idx < 2600){
        int n = idx-2560;
        float t1=0.f, t0=0.f;
        for(int c=0;c<CZ;c++){
            float wv = (n<8)?Wpb[c*8+n]:Wpo[c*32+n-8];
            t1 += lnw[c]*wv; t0 += lnb[c]*wv;
        }
        g_T1[n]=t1; g_T0[n]=t0;
    }
}

// ---- concat projection weights ----
__global__ __launch_bounds__(256) void k_wcat(const float* __restrict__ Wq, const float* __restrict__ Wk,
                                              const float* __restrict__ Wv, const float* __restrict__ Wqp,
                                              const float* __restrict__ Wkp, const float* __restrict__ Wvp){
    int idx = blockIdx.x*256 + threadIdx.x;
    int k = idx/NPROJ, n = idx%NPROJ;
    float v;
    if      (n < 256)  v = Wq [k*256 + n];
    else if (n < 512)  v = Wk [k*256 + n-256];
    else if (n < 768)  v = Wv [k*256 + n-512];
    else if (n < 864)  v = Wqp[k*96  + n-768];
    else if (n < 960)  v = Wkp[k*96  + n-864];
    else               v = Wvp[k*192 + n-960];
    g_Wcat[idx] = v;
}

// ---- SGEMM ----
__global__ __launch_bounds__(256) void k_sgemm2(const float* __restrict__ A,
                                                const float* __restrict__ W,
                                                const float* __restrict__ bias,
                                                const float* __restrict__ msk,
                                                float* __restrict__ C,
                                                int M, int N, int K){
    __shared__ float As[16][68], Bs[16][68];
    int tid = threadIdx.x;
    int tx = tid&15, ty = tid>>4;
    const float* Ab = A + (long)(blockIdx.y*64)*K;
    const float* Wb = W + blockIdx.x*64;
    float acc[4][4];
    #pragma unroll
    for(int u=0;u<4;u++)
        #pragma unroll
        for(int w2=0;w2<4;w2++) acc[u][w2]=0.f;

    int ar = tid>>2, ak = (tid&3)*4;
    int bk = tid>>4, bn = (tid&15)*4;
    float4 a4 = *(const float4*)&Ab[ar*K + ak];
    float4 b4 = *(const float4*)&Wb[(long)bk*N + bn];

    for(int k0=0;k0<K;k0+=16){
        As[ak+0][ar]=a4.x; As[ak+1][ar]=a4.y; As[ak+2][ar]=a4.z; As[ak+3][ar]=a4.w;
        *(float4*)&Bs[bk][bn]=b4;
        __syncthreads();
        if (k0+16 < K){
            a4 = *(const float4*)&Ab[ar*K + k0+16 + ak];
            b4 = *(const float4*)&Wb[(long)(k0+16+bk)*N + bn];
        }
        #pragma unroll
        for(int kk=0;kk<16;kk++){
            float4 av=*(const float4*)&As[kk][ty*4];
            float4 bv=*(const float4*)&Bs[kk][tx*4];
            float aa[4]={av.x,av.y,av.z,av.w};
            float bb[4]={bv.x,bv.y,bv.z,bv.w};
            #pragma unroll
            for(int u=0;u<4;u++)
                #pragma unroll
                for(int w2=0;w2<4;w2++) acc[u][w2] += aa[u]*bb[w2];
        }
        __syncthreads();
    }
    int gm0 = blockIdx.y*64 + ty*4, gn0 = blockIdx.x*64 + tx*4;
    #pragma unroll
    for(int u=0;u<4;u++){
        int gm = gm0+u;
        float mv = msk ? msk[gm] : 1.f;
        #pragma unroll
        for(int w2=0;w2<4;w2++){
            int gn = gn0+w2;
            float vv = acc[u][w2];
            if (bias) vv += bias[gn];
            C[(long)gm*N+gn] = vv*mv;
        }
    }
}

// ---- transpose k ----
__global__ __launch_bounds__(256) void k_transpose_k(){
    __shared__ float tile[32][33];
    int c0=blockIdx.x*32, j0=blockIdx.y*32;
    int tx=threadIdx.x&31, ty=threadIdx.x>>5;
    for(int r=ty;r<32;r+=8) tile[r][tx]=g_proj[(j0+r)*NPROJ + OFF_K + c0+tx];
    __syncthreads();
    for(int r=ty;r<32;r+=8) g_kt[(c0+r)*LL+j0+tx]=tile[tx][r];
}

// ---- rigid transform ----
__global__ __launch_bounds__(128) void k_transform(const float* __restrict__ R,
                                                   const float* __restrict__ t){
    int i=blockIdx.x, tid=threadIdx.x;
    __shared__ float Rl[9], tl[3];
    if(tid<9) Rl[tid]=R[i*9+tid];
    if(tid<3) tl[tid]=t[i*3+tid];
    __syncthreads();
    if (tid<32){
        const float* src = g_proj + i*NPROJ + OFF_QPL + tid*3;
        float p0=src[0], p1=src[1], p2=src[2];
        float gx=Rl[0]*p0+Rl[1]*p1+Rl[2]*p2+tl[0];
        float gy=Rl[3]*p0+Rl[4]*p1+Rl[5]*p2+tl[1];
        float gz=Rl[6]*p0+Rl[7]*p1+Rl[8]*p2+tl[2];
        g_qpg[i*96+tid*3]=gx; g_qpg[i*96+tid*3+1]=gy; g_qpg[i*96+tid*3+2]=gz;
        float sq=gx*gx+gy*gy+gz*gz;
        sq += __shfl_xor_sync(~0u,sq,1); sq += __shfl_xor_sync(~0u,sq,2);
        if((tid&3)==0) g_qn[i*NH+(tid>>2)]=sq;
    } else if (tid<64){
        int idx=tid-32;
        const float* src = g_proj + i*NPROJ + OFF_KPL + idx*3;
        float p0=src[0], p1=src[1], p2=src[2];
        float gx=Rl[0]*p0+Rl[1]*p1+Rl[2]*p2+tl[0];
        float gy=Rl[3]*p0+Rl[4]*p1+Rl[5]*p2+tl[1];
        float gz=Rl[6]*p0+Rl[7]*p1+Rl[8]*p2+tl[2];
        g_kpgt[(idx*3+0)*LL+i]=gx; g_kpgt[(idx*3+1)*LL+i]=gy; g_kpgt[(idx*3+2)*LL+i]=gz;
        float sq=gx*gx+gy*gy+gz*gz;
        sq += __shfl_xor_sync(~0u,sq,1); sq += __shfl_xor_sync(~0u,sq,2);
        if((idx&3)==0) g_knt[(idx>>2)*LL+i]=sq;
    } else {
        int idx=tid-64;
        const float* src = g_proj + i*NPROJ + OFF_VPL + idx*3;
        float p0=src[0], p1=src[1], p2=src[2];
        g_vpg[i*192+idx*3+0]=Rl[0]*p0+Rl[1]*p1+Rl[2]*p2+tl[0];
        g_vpg[i*192+idx*3+1]=Rl[3]*p0+Rl[4]*p1+Rl[5]*p2+tl[1];
        g_vpg[i*192+idx*3+2]=Rl[6]*p0+Rl[7]*p1+Rl[8]*p2+tl[2];
    }
}

// ---- z pass on HMMA (mma.sync bf16-split): z read once -> pair_bias + pair_v ----
__global__ __launch_bounds__(256) void k_zpass_mma(const float* __restrict__ z){
    extern __shared__ __align__(16) char smem[];
    unsigned* AH = (unsigned*)(smem + OFF_AH);
    unsigned* AL = (unsigned*)(smem + OFF_AL);
    unsigned* BF = (unsigned*)(smem + OFF_BF);
    unsigned* BL = (unsigned*)(smem + OFF_BFL);
    float* SUM = (float*)(smem + OFF_SUM);
    float* SQ  = (float*)(smem + OFF_SQ);
    float* T1s = (float*)(smem + OFF_T1S);
    float* T0s = (float*)(smem + OFF_T0S);
    int tid=threadIdx.x, wid=tid>>5, lane=tid&31;
    long pair0=(long)blockIdx.x*ZROWS;
    int irow=(int)(pair0/LL), j0=(int)(pair0%LL);

    if (tid<40){ T1s[tid]=g_T1[tid]; T0s[tid]=g_T0[tid]; }
    // stage B fragment table (hi+lo, 5120 words)
    {
        const uint4* src=(const uint4*)g_Bfrag;
        uint4* dst=(uint4*)BF;
        #pragma unroll
        for(int l=0;l<5;l++) dst[tid + l*256] = src[tid + l*256];
    }
    // stage A: stats + bf16 split into fragment layout
    {
        int ktp = lane>>2;
        #pragma unroll 4
        for(int f=0;f<16;f++){
            int row = f*8 + wid;
            float4 v = *(const float4*)&z[(pair0+row)*CZ + lane*4];
            float s4 = v.x+v.y+v.z+v.w;
            float q4 = v.x*v.x+v.y*v.y+v.z*v.z+v.w*v.w;
            #pragma unroll
            for(int o=16;o;o>>=1){ s4+=__shfl_xor_sync(~0u,s4,o); q4+=__shfl_xor_sync(~0u,q4,o); }
            if(lane==0){ SUM[row]=s4; SQ[row]=q4; }
            int i4 = row & 15, ih = i4>>3, gg = row & 7, mt = row>>4;
            int base = (mt*8+ktp)*132;
            // pair 0: cols (4*lane, 4*lane+1)
            {
                int j = (lane*4) & 15;
                int t4 = (j&7)>>1, reg = ih + 2*(j>>3);
                int w = base + (gg*4+t4)*4 + reg;
                __nv_bfloat16 h0=__float2bfloat16(v.x), h1=__float2bfloat16(v.y);
                AH[w] = pkbf(__bfloat162float(h0), __bfloat162float(h1));
                AL[w] = pkbf(v.x-__bfloat162float(h0), v.y-__bfloat162float(h1));
            }
            // pair 1: cols (4*lane+2, 4*lane+3)
            {
                int j = (lane*4+2) & 15;
                int t4 = (j&7)>>1, reg = ih + 2*(j>>3);
                int w = base + (gg*4+t4)*4 + reg;
                __nv_bfloat16 h0=__float2bfloat16(v.z), h1=__float2bfloat16(v.w);
                AH[w] = pkbf(__bfloat162float(h0), __bfloat162float(h1));
                AL[w] = pkbf(v.z-__bfloat162float(h0), v.w-__bfloat162float(h1));
            }
        }
    }
    __syncthreads();

    // MMA mainloop: warp wid owns M-tile mt=wid (rows mt*16..mt*16+15)
    float acc[5][4];
    #pragma unroll
    for(int nt=0;nt<5;nt++)
        #pragma unroll
        for(int u=0;u<4;u++) acc[nt][u]=0.f;
    int mt = wid;
    #pragma unroll
    for(int kt=0;kt<8;kt++){
        unsigned ah[4], al[4];
        *(uint4*)ah = *(const uint4*)&AH[(mt*8+kt)*132 + lane*4];
        *(uint4*)al = *(const uint4*)&AL[(mt*8+kt)*132 + lane*4];
        #pragma unroll
        for(int nt=0;nt<5;nt++){
            unsigned bh[2], bl[2];
            int bidx = ((kt*5+nt)*32 + lane)*2;
            *(uint2*)bh = *(const uint2*)&BF[bidx];
            *(uint2*)bl = *(const uint2*)&BL[bidx];
            mma16816(acc[nt], ah, bh);
            mma16816(acc[nt], ah, bl);
            mma16816(acc[nt], al, bh);
        }
    }

    // epilogue: LN fold + write pb / pv
    {
        int fg = lane>>2, ft4 = lane&3;
        int r0 = mt*16 + fg, r1 = r0 + 8;
        float m0 = SUM[r0]*(1.f/128.f), m1 = SUM[r1]*(1.f/128.f);
        float rs0 = rsqrtf(SQ[r0]*(1.f/128.f) - m0*m0 + 1e-5f);
        float rs1 = rsqrtf(SQ[r1]*(1.f/128.f) - m1*m1 + 1e-5f);
        #pragma unroll
        for(int nt=0;nt<5;nt++){
            int n0 = nt*8 + ft4*2;
            float o00 = rs0*(acc[nt][0] - m0*T1s[n0])   + T0s[n0];
            float o01 = rs0*(acc[nt][1] - m0*T1s[n0+1]) + T0s[n0+1];
            float o10 = rs1*(acc[nt][2] - m1*T1s[n0])   + T0s[n0];
            float o11 = rs1*(acc[nt][3] - m1*T1s[n0+1]) + T0s[n0+1];
            if (nt==0){
                g_pb[((long)n0*LL+irow)*LL + j0 + r0]     = o00;
                g_pb[((long)(n0+1)*LL+irow)*LL + j0 + r0] = o01;
                g_pb[((long)n0*LL+irow)*LL + j0 + r1]     = o10;
                g_pb[((long)(n0+1)*LL+irow)*LL + j0 + r1] = o11;
            } else {
                float2 w0 = make_float2(o00,o01);
                float2 w1 = make_float2(o10,o11);
                *(float2*)&g_pv[(pair0+r0)*32 + n0-8] = w0;
                *(float2*)&g_pv[(pair0+r1)*32 + n0-8] = w1;
            }
        }
    }
}

// ---- fused logits + softmax -> attn ----
__global__ __launch_bounds__(256) void k_logits_softmax(const float* __restrict__ mask,
                                                        const float* __restrict__ pweights,
                                                        float* __restrict__ attn){
    int h=blockIdx.y, i0=blockIdx.x*4, tid=threadIdx.x;
    __shared__ float qv[4][32], qp[4][12], qnv[4], mi[4], red[8][4], bmax[4], brcp[4], s_pw;
    if(tid<128){ int ii=tid>>5, c=tid&31; qv[ii][c]=g_proj[(i0+ii)*NPROJ + OFF_Q + h*32+c]; }
    else if(tid<176){ int l=tid-128, ii=l/12, pp=l%12; qp[ii][pp]=g_qpg[(i0+ii)*96+h*12+pp]; }
    else if(tid<180){ int ii=tid-176; qnv[ii]=g_qn[(i0+ii)*NH+h]; mi[ii]=mask[i0+ii]; }
    else if(tid==180){ float xw=pweights[h]; s_pw=0.5f*log1pf(expf(xw)); }
    __syncthreads();

    float lv[3][4];
    const float invs = 0.17677669529663687f;
    #pragma unroll
    for(int jj=0;jj<3;jj++){
        int j=jj*256+tid;
        float sl[4]={0,0,0,0};
        const float* kt = g_kt + h*32*LL + j;
        #pragma unroll
        for(int c=0;c<32;c++){
            float kc=kt[c*LL];
            sl[0]+=qv[0][c]*kc; sl[1]+=qv[1][c]*kc; sl[2]+=qv[2][c]*kc; sl[3]+=qv[3][c]*kc;
        }
        float pd[4]={0,0,0,0};
        const float* kp = g_kpgt + h*12*LL + j;
        #pragma unroll
        for(int pp=0;pp<12;pp++){
            float kc=kp[pp*LL];
            pd[0]+=qp[0][pp]*kc; pd[1]+=qp[1][pp]*kc; pd[2]+=qp[2][pp]*kc; pd[3]+=qp[3][pp]*kc;
        }
        float knj=g_knt[h*LL+j], mj=mask[j];
        const float* pbp = g_pb + ((long)h*LL+i0)*LL + j;
        #pragma unroll
        for(int ii=0;ii<4;ii++){
            float lg = sl[ii]*invs + pbp[(long)ii*LL] - s_pw*(qnv[ii]+knj-2.f*pd[ii]);
            if (mi[ii]*mj==0.f) lg=-1e9f;
            lv[jj][ii]=lg;
        }
    }
    #pragma unroll
    for(int ii=0;ii<4;ii++){
        float m=fmaxf(fmaxf(lv[0][ii],lv[1][ii]),lv[2][ii]);
        #pragma unroll
        for(int o=16;o;o>>=1) m=fmaxf(m,__shfl_xor_sync(~0u,m,o));
        if((tid&31)==0) red[tid>>5][ii]=m;
    }
    __syncthreads();
    if(tid<4){ float m=red[0][tid]; for(int w=1;w<8;w++)m=fmaxf(m,red[w][tid]); bmax[tid]=m; }
    __syncthreads();
    float ev[3][4], sm[4]={0,0,0,0};
    #pragma unroll
    for(int jj=0;jj<3;jj++)
        #pragma unroll
        for(int ii=0;ii<4;ii++){ float e=__expf(lv[jj][ii]-bmax[ii]); ev[jj][ii]=e; sm[ii]+=e; }
    __syncthreads();
    #pragma unroll
    for(int ii=0;ii<4;ii++){
        float s=sm[ii];
        #pragma unroll
        for(int o=16;o;o>>=1) s+=__shfl_xor_sync(~0u,s,o);
        if((tid&31)==0) red[tid>>5][ii]=s;
    }
    __syncthreads();
    if(tid<4){ float s=0; for(int w=0;w<8;w++)s+=red[w][tid]; brcp[tid]=1.f/s; }
    __syncthreads();
    #pragma unroll
    for(int jj=0;jj<3;jj++){
        int j=jj*256+tid;
        #pragma unroll
        for(int ii=0;ii<4;ii++)
            attn[((long)h*LL+i0+ii)*LL+j]=ev[jj][ii]*brcp[ii];
    }
}

// ---- fused attn @ [V | v_pts_global] ----
__global__ __launch_bounds__(256) void k_attn_fused(const float* __restrict__ attn,
                                                    const float* __restrict__ V1,
                                                    const float* __restrict__ V2){
    int h=blockIdx.y, i0=blockIdx.x*16, tid=threadIdx.x;
    __shared__ float As[16][33], Vs[32][64];
    int n=tid&63, iw=tid>>6;
    float a0=0.f,a1=0.f,a2=0.f,a3=0.f;
    for(int j0=0;j0<LL;j0+=32){
        for(int l=tid;l<512;l+=256){
            int r=l>>5, jj=l&31;
            As[r][jj]=attn[((long)h*LL+i0+r)*LL+j0+jj];
        }
        for(int l=tid;l<2048;l+=256){
            int r=l>>6, c=l&63;
            float v;
            if (c<32)      v = V1[(long)(j0+r)*NPROJ + h*32 + c];
            else if (c<56) v = V2[(long)(j0+r)*192   + h*24 + (c-32)];
            else           v = 0.f;
            Vs[r][c]=v;
        }
        __syncthreads();
        #pragma unroll
        for(int jj=0;jj<32;jj++){
            float vv=Vs[jj][n];
            a0+=As[iw][jj]*vv; a1+=As[iw+4][jj]*vv;
            a2+=As[iw+8][jj]*vv; a3+=As[iw+12][jj]*vv;
        }
        __syncthreads();
    }
    if (n<32){
        g_feat[(i0+iw)   *FEAT + h*32+n]=a0;
        g_feat[(i0+iw+4) *FEAT + h*32+n]=a1;
        g_feat[(i0+iw+8) *FEAT + h*32+n]=a2;
        g_feat[(i0+iw+12)*FEAT + h*32+n]=a3;
    } else if (n<56){
        int c=n-32;
        g_ptg[(i0+iw)   *192 + h*24+c]=a0;
        g_ptg[(i0+iw+4) *192 + h*24+c]=a1;
        g_ptg[(i0+iw+8) *192 + h*24+c]=a2;
        g_ptg[(i0+iw+12)*192 + h*24+c]=a3;
    }
}

// ---- pair_out ----
__global__ __launch_bounds__(256) void k_pair_out(const float* __restrict__ attn){
    int i=blockIdx.x, tid=threadIdx.x;
    int o=tid&31, jw=tid>>5, h=o>>2;
    float acc=0.f;
    for(int j=jw;j<LL;j+=8)
        acc += attn[((long)h*LL+i)*LL+j]*g_pv[((long)i*LL+j)*32+o];
    __shared__ float red[8][32];
    red[jw][o]=acc;
    __syncthreads();
    if(tid<32){
        float s=0; for(int w=0;w<8;w++)s+=red[w][tid];
        g_feat[i*FEAT+512+tid]=s;
    }
}

// ---- back to local frame + norms ----
__global__ __launch_bounds__(64) void k_local(const float* __restrict__ R,
                                              const float* __restrict__ t){
    int i=blockIdx.x, tid=threadIdx.x;
    __shared__ float Rl[9], tl[3];
    if(tid<9) Rl[tid]=R[i*9+tid];
    if(tid<3) tl[tid]=t[i*3+tid];
    __syncthreads();
    float gx=g_ptg[i*192+tid*3]  -tl[0];
    float gy=g_ptg[i*192+tid*3+1]-tl[1];
    float gz=g_ptg[i*192+tid*3+2]-tl[2];
    float lx=Rl[0]*gx+Rl[3]*gy+Rl[6]*gz;
    float ly=Rl[1]*gx+Rl[4]*gy+Rl[7]*gz;
    float lz=Rl[2]*gx+Rl[5]*gy+Rl[8]*gz;
    g_feat[i*FEAT+256+tid*3]  =lx;
    g_feat[i*FEAT+256+tid*3+1]=ly;
    g_feat[i*FEAT+256+tid*3+2]=lz;
    g_feat[i*FEAT+448+tid]=sqrtf(lx*lx+ly*ly+lz*lz+1e-8f);
}

extern "C" void kernel_launch(void* const* d_in, const int* in_sizes, int n_in,
                              void* d_out, int out_size){
    const float* s      =(const float*)d_in[0];
    const float* z      =(const float*)d_in[1];
    const float* R      =(const float*)d_in[2];
    const float* t      =(const float*)d_in[3];
    const float* mask   =(const float*)d_in[4];
    const float* ln_s_w =(const float*)d_in[5];
    const float* ln_s_b =(const float*)d_in[6];
    const float* ln_z_w =(const float*)d_in[7];
    const float* ln_z_b =(const float*)d_in[8];
    const float* Wq     =(const float*)d_in[9];
    const float* Wk     =(const float*)d_in[10];
    const float* Wv     =(const float*)d_in[11];
    const float* Wpb    =(const float*)d_in[12];
    const float* Wq_pts =(const float*)d_in[13];
    const float* Wk_pts =(const float*)d_in[14];
    const float* Wv_pts =(const float*)d_in[15];
    const float* pw     =(const float*)d_in[16];
    const float* Wpo    =(const float*)d_in[17];
    const float* W_out  =(const float*)d_in[18];
    const float* b_out  =(const float*)d_in[19];
    float* out  = (float*)d_out;
    float* attn = out + ATTN_OFF;

    float *p_sln,*p_wcat,*p_proj,*p_vpg,*p_feat;
    cudaGetSymbolAddress((void**)&p_sln,  g_sln);
    cudaGetSymbolAddress((void**)&p_wcat, g_Wcat);
    cudaGetSymbolAddress((void**)&p_proj, g_proj);
    cudaGetSymbolAddress((void**)&p_vpg,  g_vpg);
    cudaGetSymbolAddress((void**)&p_feat, g_feat);

    static cudaStream_t sB = nullptr;
    static cudaEvent_t evF1=nullptr, evJ1=nullptr;
    if (sB == nullptr){
        cudaStreamCreateWithFlags(&sB, cudaStreamNonBlocking);
        cudaEventCreateWithFlags(&evF1, cudaEventDisableTiming);
        cudaEventCreateWithFlags(&evJ1, cudaEventDisableTiming);
        cudaFuncSetAttribute(k_zpass_mma, cudaFuncAttributeMaxDynamicSharedMemorySize, SMEM_Z);
    }

    // fork 1: projection chain (sB) || z pass (s0)
    cudaEventRecord(evF1, 0);
    cudaStreamWaitEvent(sB, evF1, 0);

    k_ln_s<<<LL,256,0,sB>>>(s, ln_s_w, ln_s_b);
    k_wcat<<<(CS*NPROJ)/256,256,0,sB>>>(Wq, Wk, Wv, Wq_pts, Wk_pts, Wv_pts);
    k_sgemm2<<<dim3(NPROJ/64, LL/64),256,0,sB>>>(p_sln, p_wcat, nullptr, nullptr, p_proj, LL, NPROJ, CS);
    k_transpose_k<<<dim3(8,24),256,0,sB>>>();
    k_transform<<<LL,128,0,sB>>>(R, t);
    cudaEventRecord(evJ1, sB);

    k_premix<<<11,256>>>(ln_z_w, ln_z_b, Wpb, Wpo);
    k_zpass_mma<<<(LL*LL)/ZROWS,256,SMEM_Z>>>(z);

    cudaStreamWaitEvent(0, evJ1, 0);
    k_logits_softmax<<<dim3(LL/4,NH),256>>>(mask, pw, attn);
    k_attn_fused<<<dim3(LL/16,NH),256>>>(attn, p_proj + OFF_V, p_vpg);
    k_pair_out<<<LL,256>>>(attn);
    k_local<<<LL,64>>>(R, t);
    k_sgemm2<<<dim3(CS/64, LL/64),256>>>(p_feat, W_out, b_out, mask, out, LL, CS, FEAT);
}

// round 16
// speedup vs baseline: 1.3363x; 1.0202x over previous
#include <cuda_runtime.h>
#include <cuda_bf16.h>
#include <cstdint>
#include <stdint.h>
#include <math.h>

#define LL 768
#define CS 256
#define CZ 128
#define NH 8
#define FEAT 544
#define NPROJ 1152
#define ATTN_OFF (LL*CS)

#define OFF_Q   0
#define OFF_K   256
#define OFF_V   512
#define OFF_QPL 768
#define OFF_KPL 864
#define OFF_VPL 960

typedef unsigned long long ull;

__device__ float g_sln[LL*CS];
__device__ float g_Wcat[CS*NPROJ];
__device__ float g_proj[LL*NPROJ];
__device__ float g_kt[CS*LL];
__device__ float g_qpg[LL*96];
__device__ float g_kpgt[96*LL];
__device__ float g_vpg[LL*192];
__device__ float g_qn[LL*NH];
__device__ float g_knt[NH*LL];
__device__ float g_pb[(long)NH*LL*LL];
__device__ float g_pv[(long)LL*LL*32];
__device__ float g_feat[LL*FEAT];
__device__ float g_ptg[LL*192];
__device__ float g_T1[40];
__device__ float g_T0[40];
__device__ unsigned g_Bfrag[5120];      // [hi:0..2559 | lo:2560..5119] B fragments

// ---------------- zpass_mma smem layout (bytes) ----------------
#define ZROWS 128
#define OFF_AH  0
#define OFF_AL  33792
#define OFF_BF  67584
#define OFF_BFL 77824
#define OFF_SUM 88064
#define OFF_SQ  88576
#define OFF_T1S 89088
#define OFF_T0S 89248
#define SMEM_Z  89408

__device__ __forceinline__ void mma16816(float* d, const unsigned* a, const unsigned* b){
    asm volatile("mma.sync.aligned.m16n8k16.row.col.f32.bf16.bf16.f32 "
        "{%0,%1,%2,%3}, {%4,%5,%6,%7}, {%8,%9}, {%0,%1,%2,%3};"
        : "+f"(d[0]),"+f"(d[1]),"+f"(d[2]),"+f"(d[3])
        : "r"(a[0]),"r"(a[1]),"r"(a[2]),"r"(a[3]), "r"(b[0]),"r"(b[1]));
}
__device__ __forceinline__ unsigned pkbf(float x, float y){
    __nv_bfloat162 h = __floats2bfloat162_rn(x, y);
    return *(unsigned*)&h;
}

// ---- LN of s ----
__global__ __launch_bounds__(256) void k_ln_s(const float* __restrict__ s,
                                              const float* __restrict__ w,
                                              const float* __restrict__ b){
    int i = blockIdx.x, t = threadIdx.x;
    float x = s[i*CS + t];
    __shared__ float sh[8]; __shared__ float s_m, s_r;
    float v = x;
    #pragma unroll
    for (int o=16;o;o>>=1) v += __shfl_xor_sync(~0u,v,o);
    if ((t&31)==0) sh[t>>5]=v;
    __syncthreads();
    if (t==0){ float u=0; for(int kk=0;kk<8;kk++)u+=sh[kk]; s_m=u*(1.f/256.f); }
    __syncthreads();
    float d = x - s_m; v = d*d;
    #pragma unroll
    for (int o=16;o;o>>=1) v += __shfl_xor_sync(~0u,v,o);
    if ((t&31)==0) sh[t>>5]=v;
    __syncthreads();
    if (t==0){ float u=0; for(int kk=0;kk<8;kk++)u+=sh[kk]; s_r=rsqrtf(u*(1.f/256.f)+1e-5f); }
    __syncthreads();
    g_sln[i*CS+t] = d*s_r*w[t] + b[t];
}

// ---- premix: B fragment table (bf16 split) + T1/T0 ----
__global__ void k_premix(const float* __restrict__ lnw, const float* __restrict__ lnb,
                         const float* __restrict__ Wpb, const float* __restrict__ Wpo){
    int idx = blockIdx.x*256 + threadIdx.x;
    if (idx < 2560){
        int breg = idx & 1;
        int r    = idx >> 1;
        int lane = r & 31;
        int q    = r >> 5;
        int nt   = q % 5;
        int kt   = q / 5;
        int g  = lane >> 2, t4 = lane & 3;
        int k  = kt*16 + t4*2 + breg*8;
        int n  = nt*8 + g;
        float w0 = lnw[k]  *((n<8)?Wpb[k*8+n]    :Wpo[k*32+n-8]);
        float w1 = lnw[k+1]*((n<8)?Wpb[(k+1)*8+n]:Wpo[(k+1)*32+n-8]);
        __nv_bfloat16 h0 = __float2bfloat16(w0), h1 = __float2bfloat16(w1);
        float l0 = w0 - __bfloat162float(h0), l1 = w1 - __bfloat162float(h1);
        g_Bfrag[idx]        = pkbf(__bfloat162float(h0), __bfloat162float(h1));
        g_Bfrag[2560 + idx] = pkbf(l0, l1);
    } else if (idx < 2600){
        int n = idx-2560;
        float t1=0.f, t0=0.f;
        for(int c=0;c<CZ;c++){
            float wv = (n<8)?Wpb[c*8+n]:Wpo[c*32+n-8];
            t1 += lnw[c]*wv; t0 += lnb[c]*wv;
        }
        g_T1[n]=t1; g_T0[n]=t0;
    }
}

// ---- concat projection weights ----
__global__ __launch_bounds__(256) void k_wcat(const float* __restrict__ Wq, const float* __restrict__ Wk,
                                              const float* __restrict__ Wv, const float* __restrict__ Wqp,
                                              const float* __restrict__ Wkp, const float* __restrict__ Wvp){
    int idx = blockIdx.x*256 + threadIdx.x;
    int k = idx/NPROJ, n = idx%NPROJ;
    float v;
    if      (n < 256)  v = Wq [k*256 + n];
    else if (n < 512)  v = Wk [k*256 + n-256];
    else if (n < 768)  v = Wv [k*256 + n-512];
    else if (n < 864)  v = Wqp[k*96  + n-768];
    else if (n < 960)  v = Wkp[k*96  + n-864];
    else               v = Wvp[k*192 + n-960];
    g_Wcat[idx] = v;
}

// ---- SGEMM 64x64 (projection) ----
__global__ __launch_bounds__(256) void k_sgemm2(const float* __restrict__ A,
                                                const float* __restrict__ W,
                                                const float* __restrict__ bias,
                                                const float* __restrict__ msk,
                                                float* __restrict__ C,
                                                int M, int N, int K){
    __shared__ float As[16][68], Bs[16][68];
    int tid = threadIdx.x;
    int tx = tid&15, ty = tid>>4;
    const float* Ab = A + (long)(blockIdx.y*64)*K;
    const float* Wb = W + blockIdx.x*64;
    float acc[4][4];
    #pragma unroll
    for(int u=0;u<4;u++)
        #pragma unroll
        for(int w2=0;w2<4;w2++) acc[u][w2]=0.f;

    int ar = tid>>2, ak = (tid&3)*4;
    int bk = tid>>4, bn = (tid&15)*4;
    float4 a4 = *(const float4*)&Ab[ar*K + ak];
    float4 b4 = *(const float4*)&Wb[(long)bk*N + bn];

    for(int k0=0;k0<K;k0+=16){
        As[ak+0][ar]=a4.x; As[ak+1][ar]=a4.y; As[ak+2][ar]=a4.z; As[ak+3][ar]=a4.w;
        *(float4*)&Bs[bk][bn]=b4;
        __syncthreads();
        if (k0+16 < K){
            a4 = *(const float4*)&Ab[ar*K + k0+16 + ak];
            b4 = *(const float4*)&Wb[(long)(k0+16+bk)*N + bn];
        }
        #pragma unroll
        for(int kk=0;kk<16;kk++){
            float4 av=*(const float4*)&As[kk][ty*4];
            float4 bv=*(const float4*)&Bs[kk][tx*4];
            float aa[4]={av.x,av.y,av.z,av.w};
            float bb[4]={bv.x,bv.y,bv.z,bv.w};
            #pragma unroll
            for(int u=0;u<4;u++)
                #pragma unroll
                for(int w2=0;w2<4;w2++) acc[u][w2] += aa[u]*bb[w2];
        }
        __syncthreads();
    }
    int gm0 = blockIdx.y*64 + ty*4, gn0 = blockIdx.x*64 + tx*4;
    #pragma unroll
    for(int u=0;u<4;u++){
        int gm = gm0+u;
        float mv = msk ? msk[gm] : 1.f;
        #pragma unroll
        for(int w2=0;w2<4;w2++){
            int gn = gn0+w2;
            float vv = acc[u][w2];
            if (bias) vv += bias[gn];
            C[(long)gm*N+gn] = vv*mv;
        }
    }
}

// ---- SGEMM 32x64 tiles (final projection; higher occupancy, K%16==0, M%32==0, N%64==0) ----
__global__ __launch_bounds__(256) void k_sgemm3(const float* __restrict__ A,
                                                const float* __restrict__ W,
                                                const float* __restrict__ bias,
                                                const float* __restrict__ msk,
                                                float* __restrict__ C,
                                                int M, int N, int K){
    __shared__ float As[16][36], Bs[16][68];
    int tid = threadIdx.x;
    int tx = tid&15, ty = tid>>4;
    const float* Ab = A + (long)(blockIdx.y*32)*K;
    const float* Wb = W + blockIdx.x*64;
    float acc[2][4];
    #pragma unroll
    for(int u=0;u<2;u++)
        #pragma unroll
        for(int w2=0;w2<4;w2++) acc[u][w2]=0.f;

    int ar = tid>>3, ak = (tid&7)*2;
    int bk = tid>>4, bn = (tid&15)*4;
    float2 a2 = *(const float2*)&Ab[ar*K + ak];
    float4 b4 = *(const float4*)&Wb[(long)bk*N + bn];

    for(int k0=0;k0<K;k0+=16){
        As[ak+0][ar]=a2.x; As[ak+1][ar]=a2.y;
        *(float4*)&Bs[bk][bn]=b4;
        __syncthreads();
        if (k0+16 < K){
            a2 = *(const float2*)&Ab[ar*K + k0+16 + ak];
            b4 = *(const float4*)&Wb[(long)(k0+16+bk)*N + bn];
        }
        #pragma unroll
        for(int kk=0;kk<16;kk++){
            float2 av=*(const float2*)&As[kk][ty*2];
            float4 bv=*(const float4*)&Bs[kk][tx*4];
            float bb[4]={bv.x,bv.y,bv.z,bv.w};
            #pragma unroll
            for(int w2=0;w2<4;w2++){ acc[0][w2]+=av.x*bb[w2]; acc[1][w2]+=av.y*bb[w2]; }
        }
        __syncthreads();
    }
    int gm0 = blockIdx.y*32 + ty*2, gn0 = blockIdx.x*64 + tx*4;
    #pragma unroll
    for(int u=0;u<2;u++){
        int gm = gm0+u;
        float mv = msk ? msk[gm] : 1.f;
        #pragma unroll
        for(int w2=0;w2<4;w2++){
            int gn = gn0+w2;
            float vv = acc[u][w2];
            if (bias) vv += bias[gn];
            C[(long)gm*N+gn] = vv*mv;
        }
    }
}

// ---- transpose k ----
__global__ __launch_bounds__(256) void k_transpose_k(){
    __shared__ float tile[32][33];
    int c0=blockIdx.x*32, j0=blockIdx.y*32;
    int tx=threadIdx.x&31, ty=threadIdx.x>>5;
    for(int r=ty;r<32;r+=8) tile[r][tx]=g_proj[(j0+r)*NPROJ + OFF_K + c0+tx];
    __syncthreads();
    for(int r=ty;r<32;r+=8) g_kt[(c0+r)*LL+j0+tx]=tile[tx][r];
}

// ---- rigid transform ----
__global__ __launch_bounds__(128) void k_transform(const float* __restrict__ R,
                                                   const float* __restrict__ t){
    int i=blockIdx.x, tid=threadIdx.x;
    __shared__ float Rl[9], tl[3];
    if(tid<9) Rl[tid]=R[i*9+tid];
    if(tid<3) tl[tid]=t[i*3+tid];
    __syncthreads();
    if (tid<32){
        const float* src = g_proj + i*NPROJ + OFF_QPL + tid*3;
        float p0=src[0], p1=src[1], p2=src[2];
        float gx=Rl[0]*p0+Rl[1]*p1+Rl[2]*p2+tl[0];
        float gy=Rl[3]*p0+Rl[4]*p1+Rl[5]*p2+tl[1];
        float gz=Rl[6]*p0+Rl[7]*p1+Rl[8]*p2+tl[2];
        g_qpg[i*96+tid*3]=gx; g_qpg[i*96+tid*3+1]=gy; g_qpg[i*96+tid*3+2]=gz;
        float sq=gx*gx+gy*gy+gz*gz;
        sq += __shfl_xor_sync(~0u,sq,1); sq += __shfl_xor_sync(~0u,sq,2);
        if((tid&3)==0) g_qn[i*NH+(tid>>2)]=sq;
    } else if (tid<64){
        int idx=tid-32;
        const float* src = g_proj + i*NPROJ + OFF_KPL + idx*3;
        float p0=src[0], p1=src[1], p2=src[2];
        float gx=Rl[0]*p0+Rl[1]*p1+Rl[2]*p2+tl[0];
        float gy=Rl[3]*p0+Rl[4]*p1+Rl[5]*p2+tl[1];
        float gz=Rl[6]*p0+Rl[7]*p1+Rl[8]*p2+tl[2];
        g_kpgt[(idx*3+0)*LL+i]=gx; g_kpgt[(idx*3+1)*LL+i]=gy; g_kpgt[(idx*3+2)*LL+i]=gz;
        float sq=gx*gx+gy*gy+gz*gz;
        sq += __shfl_xor_sync(~0u,sq,1); sq += __shfl_xor_sync(~0u,sq,2);
        if((idx&3)==0) g_knt[(idx>>2)*LL+i]=sq;
    } else {
        int idx=tid-64;
        const float* src = g_proj + i*NPROJ + OFF_VPL + idx*3;
        float p0=src[0], p1=src[1], p2=src[2];
        g_vpg[i*192+idx*3+0]=Rl[0]*p0+Rl[1]*p1+Rl[2]*p2+tl[0];
        g_vpg[i*192+idx*3+1]=Rl[3]*p0+Rl[4]*p1+Rl[5]*p2+tl[1];
        g_vpg[i*192+idx*3+2]=Rl[6]*p0+Rl[7]*p1+Rl[8]*p2+tl[2];
    }
}

// ---- z pass on HMMA (mma.sync bf16-split): z read once -> pair_bias + pair_v ----
__global__ __launch_bounds__(256) void k_zpass_mma(const float* __restrict__ z){
    extern __shared__ __align__(16) char smem[];
    unsigned* AH = (unsigned*)(smem + OFF_AH);
    unsigned* AL = (unsigned*)(smem + OFF_AL);
    unsigned* BF = (unsigned*)(smem + OFF_BF);
    unsigned* BL = (unsigned*)(smem + OFF_BFL);
    float* SUM = (float*)(smem + OFF_SUM);
    float* SQ  = (float*)(smem + OFF_SQ);
    float* T1s = (float*)(smem + OFF_T1S);
    float* T0s = (float*)(smem + OFF_T0S);
    int tid=threadIdx.x, wid=tid>>5, lane=tid&31;
    long pair0=(long)blockIdx.x*ZROWS;
    int irow=(int)(pair0/LL), j0=(int)(pair0%LL);

    if (tid<40){ T1s[tid]=g_T1[tid]; T0s[tid]=g_T0[tid]; }
    {
        const uint4* src=(const uint4*)g_Bfrag;
        uint4* dst=(uint4*)BF;
        #pragma unroll
        for(int l=0;l<5;l++) dst[tid + l*256] = src[tid + l*256];
    }
    {
        int ktp = lane>>2;
        #pragma unroll 4
        for(int f=0;f<16;f++){
            int row = f*8 + wid;
            float4 v = *(const float4*)&z[(pair0+row)*CZ + lane*4];
            float s4 = v.x+v.y+v.z+v.w;
            float q4 = v.x*v.x+v.y*v.y+v.z*v.z+v.w*v.w;
            #pragma unroll
            for(int o=16;o;o>>=1){ s4+=__shfl_xor_sync(~0u,s4,o); q4+=__shfl_xor_sync(~0u,q4,o); }
            if(lane==0){ SUM[row]=s4; SQ[row]=q4; }
            int i4 = row & 15, ih = i4>>3, gg = row & 7, mt = row>>4;
            int base = (mt*8+ktp)*132;
            {
                int j = (lane*4) & 15;
                int t4 = (j&7)>>1, reg = ih + 2*(j>>3);
                int w = base + (gg*4+t4)*4 + reg;
                __nv_bfloat16 h0=__float2bfloat16(v.x), h1=__float2bfloat16(v.y);
                AH[w] = pkbf(__bfloat162float(h0), __bfloat162float(h1));
                AL[w] = pkbf(v.x-__bfloat162float(h0), v.y-__bfloat162float(h1));
            }
            {
                int j = (lane*4+2) & 15;
                int t4 = (j&7)>>1, reg = ih + 2*(j>>3);
                int w = base + (gg*4+t4)*4 + reg;
                __nv_bfloat16 h0=__float2bfloat16(v.z), h1=__float2bfloat16(v.w);
                AH[w] = pkbf(__bfloat162float(h0), __bfloat162float(h1));
                AL[w] = pkbf(v.z-__bfloat162float(h0), v.w-__bfloat162float(h1));
            }
        }
    }
    __syncthreads();

    float acc[5][4];
    #pragma unroll
    for(int nt=0;nt<5;nt++)
        #pragma unroll
        for(int u=0;u<4;u++) acc[nt][u]=0.f;
    int mt = wid;
    #pragma unroll
    for(int kt=0;kt<8;kt++){
        unsigned ah[4], al[4];
        *(uint4*)ah = *(const uint4*)&AH[(mt*8+kt)*132 + lane*4];
        *(uint4*)al = *(const uint4*)&AL[(mt*8+kt)*132 + lane*4];
        #pragma unroll
        for(int nt=0;nt<5;nt++){
            unsigned bh[2], bl[2];
            int bidx = ((kt*5+nt)*32 + lane)*2;
            *(uint2*)bh = *(const uint2*)&BF[bidx];
            *(uint2*)bl = *(const uint2*)&BL[bidx];
            mma16816(acc[nt], ah, bh);
            mma16816(acc[nt], ah, bl);
            mma16816(acc[nt], al, bh);
        }
    }

    {
        int fg = lane>>2, ft4 = lane&3;
        int r0 = mt*16 + fg, r1 = r0 + 8;
        float m0 = SUM[r0]*(1.f/128.f), m1 = SUM[r1]*(1.f/128.f);
        float rs0 = rsqrtf(SQ[r0]*(1.f/128.f) - m0*m0 + 1e-5f);
        float rs1 = rsqrtf(SQ[r1]*(1.f/128.f) - m1*m1 + 1e-5f);
        #pragma unroll
        for(int nt=0;nt<5;nt++){
            int n0 = nt*8 + ft4*2;
            float o00 = rs0*(acc[nt][0] - m0*T1s[n0])   + T0s[n0];
            float o01 = rs0*(acc[nt][1] - m0*T1s[n0+1]) + T0s[n0+1];
            float o10 = rs1*(acc[nt][2] - m1*T1s[n0])   + T0s[n0];
            float o11 = rs1*(acc[nt][3] - m1*T1s[n0+1]) + T0s[n0+1];
            if (nt==0){
                g_pb[((long)n0*LL+irow)*LL + j0 + r0]     = o00;
                g_pb[((long)(n0+1)*LL+irow)*LL + j0 + r0] = o01;
                g_pb[((long)n0*LL+irow)*LL + j0 + r1]     = o10;
                g_pb[((long)(n0+1)*LL+irow)*LL + j0 + r1] = o11;
            } else {
                *(float2*)&g_pv[(pair0+r0)*32 + n0-8] = make_float2(o00,o01);
                *(float2*)&g_pv[(pair0+r1)*32 + n0-8] = make_float2(o10,o11);
            }
        }
    }
}

// ---- fused logits + softmax -> attn ----
__global__ __launch_bounds__(256) void k_logits_softmax(const float* __restrict__ mask,
                                                        const float* __restrict__ pweights,
                                                        float* __restrict__ attn){
    int h=blockIdx.y, i0=blockIdx.x*4, tid=threadIdx.x;
    __shared__ float qv[4][32], qp[4][12], qnv[4], mi[4], red[8][4], bmax[4], brcp[4], s_pw;
    if(tid<128){ int ii=tid>>5, c=tid&31; qv[ii][c]=g_proj[(i0+ii)*NPROJ + OFF_Q + h*32+c]; }
    else if(tid<176){ int l=tid-128, ii=l/12, pp=l%12; qp[ii][pp]=g_qpg[(i0+ii)*96+h*12+pp]; }
    else if(tid<180){ int ii=tid-176; qnv[ii]=g_qn[(i0+ii)*NH+h]; mi[ii]=mask[i0+ii]; }
    else if(tid==180){ float xw=pweights[h]; s_pw=0.5f*log1pf(expf(xw)); }
    __syncthreads();

    float lv[3][4];
    const float invs = 0.17677669529663687f;
    #pragma unroll
    for(int jj=0;jj<3;jj++){
        int j=jj*256+tid;
        float sl[4]={0,0,0,0};
        const float* kt = g_kt + h*32*LL + j;
        #pragma unroll
        for(int c=0;c<32;c++){
            float kc=kt[c*LL];
            sl[0]+=qv[0][c]*kc; sl[1]+=qv[1][c]*kc; sl[2]+=qv[2][c]*kc; sl[3]+=qv[3][c]*kc;
        }
        float pd[4]={0,0,0,0};
        const float* kp = g_kpgt + h*12*LL + j;
        #pragma unroll
        for(int pp=0;pp<12;pp++){
            float kc=kp[pp*LL];
            pd[0]+=qp[0][pp]*kc; pd[1]+=qp[1][pp]*kc; pd[2]+=qp[2][pp]*kc; pd[3]+=qp[3][pp]*kc;
        }
        float knj=g_knt[h*LL+j], mj=mask[j];
        const float* pbp = g_pb + ((long)h*LL+i0)*LL + j;
        #pragma unroll
        for(int ii=0;ii<4;ii++){
            float lg = sl[ii]*invs + pbp[(long)ii*LL] - s_pw*(qnv[ii]+knj-2.f*pd[ii]);
            if (mi[ii]*mj==0.f) lg=-1e9f;
            lv[jj][ii]=lg;
        }
    }
    #pragma unroll
    for(int ii=0;ii<4;ii++){
        float m=fmaxf(fmaxf(lv[0][ii],lv[1][ii]),lv[2][ii]);
        #pragma unroll
        for(int o=16;o;o>>=1) m=fmaxf(m,__shfl_xor_sync(~0u,m,o));
        if((tid&31)==0) red[tid>>5][ii]=m;
    }
    __syncthreads();
    if(tid<4){ float m=red[0][tid]; for(int w=1;w<8;w++)m=fmaxf(m,red[w][tid]); bmax[tid]=m; }
    __syncthreads();
    float ev[3][4], sm[4]={0,0,0,0};
    #pragma unroll
    for(int jj=0;jj<3;jj++)
        #pragma unroll
        for(int ii=0;ii<4;ii++){ float e=__expf(lv[jj][ii]-bmax[ii]); ev[jj][ii]=e; sm[ii]+=e; }
    __syncthreads();
    #pragma unroll
    for(int ii=0;ii<4;ii++){
        float s=sm[ii];
        #pragma unroll
        for(int o=16;o;o>>=1) s+=__shfl_xor_sync(~0u,s,o);
        if((tid&31)==0) red[tid>>5][ii]=s;
    }
    __syncthreads();
    if(tid<4){ float s=0; for(int w=0;w<8;w++)s+=red[w][tid]; brcp[tid]=1.f/s; }
    __syncthreads();
    #pragma unroll
    for(int jj=0;jj<3;jj++){
        int j=jj*256+tid;
        #pragma unroll
        for(int ii=0;ii<4;ii++)
            attn[((long)h*LL+i0+ii)*LL+j]=ev[jj][ii]*brcp[ii];
    }
}

// ---- fused attn @ [V | v_pts_global], V transposed in smem, float2 over j ----
__global__ __launch_bounds__(256) void k_attn_fused(const float* __restrict__ attn,
                                                    const float* __restrict__ V1,
                                                    const float* __restrict__ V2){
    int h=blockIdx.y, i0=blockIdx.x*16, tid=threadIdx.x;
    __shared__ float As[16][34], Vs[64][34];
    int n=tid&63, iw=tid>>6;
    float a0=0.f,a1=0.f,a2=0.f,a3=0.f;
    for(int j0=0;j0<LL;j0+=32){
        for(int l=tid;l<512;l+=256){
            int r=l>>5, jj=l&31;
            As[r][jj]=attn[((long)h*LL+i0+r)*LL+j0+jj];
        }
        for(int l=tid;l<2048;l+=256){
            int r=l>>6, c=l&63;
            float v;
            if (c<32)      v = V1[(long)(j0+r)*NPROJ + h*32 + c];
            else if (c<56) v = V2[(long)(j0+r)*192   + h*24 + (c-32)];
            else           v = 0.f;
            Vs[c][r]=v;
        }
        __syncthreads();
        #pragma unroll
        for(int jj=0;jj<32;jj+=2){
            float2 vv = *(const float2*)&Vs[n][jj];
            float2 b0 = *(const float2*)&As[iw][jj];
            float2 b1 = *(const float2*)&As[iw+4][jj];
            float2 b2 = *(const float2*)&As[iw+8][jj];
            float2 b3 = *(const float2*)&As[iw+12][jj];
            a0 += b0.x*vv.x + b0.y*vv.y;
            a1 += b1.x*vv.x + b1.y*vv.y;
            a2 += b2.x*vv.x + b2.y*vv.y;
            a3 += b3.x*vv.x + b3.y*vv.y;
        }
        __syncthreads();
    }
    if (n<32){
        g_feat[(i0+iw)   *FEAT + h*32+n]=a0;
        g_feat[(i0+iw+4) *FEAT + h*32+n]=a1;
        g_feat[(i0+iw+8) *FEAT + h*32+n]=a2;
        g_feat[(i0+iw+12)*FEAT + h*32+n]=a3;
    } else if (n<56){
        int c=n-32;
        g_ptg[(i0+iw)   *192 + h*24+c]=a0;
        g_ptg[(i0+iw+4) *192 + h*24+c]=a1;
        g_ptg[(i0+iw+8) *192 + h*24+c]=a2;
        g_ptg[(i0+iw+12)*192 + h*24+c]=a3;
    }
}

// ---- pair_out ----
__global__ __launch_bounds__(256) void k_pair_out(const float* __restrict__ attn){
    int i=blockIdx.x, tid=threadIdx.x;
    int o=tid&31, jw=tid>>5, h=o>>2;
    float acc=0.f;
    for(int j=jw;j<LL;j+=8)
        acc += attn[((long)h*LL+i)*LL+j]*g_pv[((long)i*LL+j)*32+o];
    __shared__ float red[8][32];
    red[jw][o]=acc;
    __syncthreads();
    if(tid<32){
        float s=0; for(int w=0;w<8;w++)s+=red[w][tid];
        g_feat[i*FEAT+512+tid]=s;
    }
}

// ---- back to local frame + norms ----
__global__ __launch_bounds__(64) void k_local(const float* __restrict__ R,
                                              const float* __restrict__ t){
    int i=blockIdx.x, tid=threadIdx.x;
    __shared__ float Rl[9], tl[3];
    if(tid<9) Rl[tid]=R[i*9+tid];
    if(tid<3) tl[tid]=t[i*3+tid];
    __syncthreads();
    float gx=g_ptg[i*192+tid*3]  -tl[0];
    float gy=g_ptg[i*192+tid*3+1]-tl[1];
    float gz=g_ptg[i*192+tid*3+2]-tl[2];
    float lx=Rl[0]*gx+Rl[3]*gy+Rl[6]*gz;
    float ly=Rl[1]*gx+Rl[4]*gy+Rl[7]*gz;
    float lz=Rl[2]*gx+Rl[5]*gy+Rl[8]*gz;
    g_feat[i*FEAT+256+tid*3]  =lx;
    g_feat[i*FEAT+256+tid*3+1]=ly;
    g_feat[i*FEAT+256+tid*3+2]=lz;
    g_feat[i*FEAT+448+tid]=sqrtf(lx*lx+ly*ly+lz*lz+1e-8f);
}

extern "C" void kernel_launch(void* const* d_in, const int* in_sizes, int n_in,
                              void* d_out, int out_size){
    const float* s      =(const float*)d_in[0];
    const float* z      =(const float*)d_in[1];
    const float* R      =(const float*)d_in[2];
    const float* t      =(const float*)d_in[3];
    const float* mask   =(const float*)d_in[4];
    const float* ln_s_w =(const float*)d_in[5];
    const float* ln_s_b =(const float*)d_in[6];
    const float* ln_z_w =(const float*)d_in[7];
    const float* ln_z_b =(const float*)d_in[8];
    const float* Wq     =(const float*)d_in[9];
    const float* Wk     =(const float*)d_in[10];
    const float* Wv     =(const float*)d_in[11];
    const float* Wpb    =(const float*)d_in[12];
    const float* Wq_pts =(const float*)d_in[13];
    const float* Wk_pts =(const float*)d_in[14];
    const float* Wv_pts =(const float*)d_in[15];
    const float* pw     =(const float*)d_in[16];
    const float* Wpo    =(const float*)d_in[17];
    const float* W_out  =(const float*)d_in[18];
    const float* b_out  =(const float*)d_in[19];
    float* out  = (float*)d_out;
    float* attn = out + ATTN_OFF;

    float *p_sln,*p_wcat,*p_proj,*p_vpg,*p_feat;
    cudaGetSymbolAddress((void**)&p_sln,  g_sln);
    cudaGetSymbolAddress((void**)&p_wcat, g_Wcat);
    cudaGetSymbolAddress((void**)&p_proj, g_proj);
    cudaGetSymbolAddress((void**)&p_vpg,  g_vpg);
    cudaGetSymbolAddress((void**)&p_feat, g_feat);

    static cudaStream_t sB = nullptr;
    static cudaEvent_t evF1=nullptr, evJ1=nullptr;
    if (sB == nullptr){
        cudaStreamCreateWithFlags(&sB, cudaStreamNonBlocking);
        cudaEventCreateWithFlags(&evF1, cudaEventDisableTiming);
        cudaEventCreateWithFlags(&evJ1, cudaEventDisableTiming);
        cudaFuncSetAttribute(k_zpass_mma, cudaFuncAttributeMaxDynamicSharedMemorySize, SMEM_Z);
    }

    // fork 1: projection chain (sB) || z pass (s0)
    cudaEventRecord(evF1, 0);
    cudaStreamWaitEvent(sB, evF1, 0);

    k_ln_s<<<LL,256,0,sB>>>(s, ln_s_w, ln_s_b);
    k_wcat<<<(CS*NPROJ)/256,256,0,sB>>>(Wq, Wk, Wv, Wq_pts, Wk_pts, Wv_pts);
    k_sgemm2<<<dim3(NPROJ/64, LL/64),256,0,sB>>>(p_sln, p_wcat, nullptr, nullptr, p_proj, LL, NPROJ, CS);
    k_transpose_k<<<dim3(8,24),256,0,sB>>>();
    k_transform<<<LL,128,0,sB>>>(R, t);
    cudaEventRecord(evJ1, sB);

    k_premix<<<11,256>>>(ln_z_w, ln_z_b, Wpb, Wpo);
    k_zpass_mma<<<(LL*LL)/ZROWS,256,SMEM_Z>>>(z);

    cudaStreamWaitEvent(0, evJ1, 0);
    k_logits_softmax<<<dim3(LL/4,NH),256>>>(mask, pw, attn);
    k_attn_fused<<<dim3(LL/16,NH),256>>>(attn, p_proj + OFF_V, p_vpg);
    k_pair_out<<<LL,256>>>(attn);
    k_local<<<LL,64>>>(R, t);
    k_sgemm3<<<dim3(CS/64, LL/32),256>>>(p_feat, W_out, b_out, mask, out, LL, CS, FEAT);
}

// round 17
// speedup vs baseline: 1.3393x; 1.0022x over previous
#include <cuda_runtime.h>
#include <cuda_bf16.h>
#include <cstdint>
#include <stdint.h>
#include <math.h>

#define LL 768
#define CS 256
#define CZ 128
#define NH 8
#define FEAT 544
#define NPROJ 1152
#define ATTN_OFF (LL*CS)

#define OFF_Q   0
#define OFF_K   256
#define OFF_V   512
#define OFF_QPL 768
#define OFF_KPL 864
#define OFF_VPL 960

typedef unsigned long long ull;

__device__ float g_sln[LL*CS];
__device__ float g_Wcat[CS*NPROJ];
__device__ float g_proj[LL*NPROJ];
__device__ float g_kt[CS*LL];
__device__ float g_qpg[LL*96];
__device__ float g_kpgt[96*LL];
__device__ float g_vpg[LL*192];
__device__ float g_qn[LL*NH];
__device__ float g_knt[NH*LL];
__device__ float g_pb[(long)NH*LL*LL];
__device__ float g_pv[(long)LL*LL*32];
__device__ float g_feat[LL*FEAT];
__device__ float g_ptg[LL*192];
__device__ float g_T1[40];
__device__ float g_T0[40];
__device__ unsigned g_Bfrag[5120];      // [hi:0..2559 | lo:2560..5119] B fragments

// ---------------- zpass_mma smem layout (bytes) ----------------
#define ZROWS 128
#define OFF_AH  0
#define OFF_AL  33792
#define OFF_BF  67584
#define OFF_BFL 77824
#define OFF_SUM 88064
#define OFF_SQ  88576
#define OFF_T1S 89088
#define OFF_T0S 89248
#define SMEM_Z  89408

__device__ __forceinline__ void mma16816(float* d, const unsigned* a, const unsigned* b){
    asm volatile("mma.sync.aligned.m16n8k16.row.col.f32.bf16.bf16.f32 "
        "{%0,%1,%2,%3}, {%4,%5,%6,%7}, {%8,%9}, {%0,%1,%2,%3};"
        : "+f"(d[0]),"+f"(d[1]),"+f"(d[2]),"+f"(d[3])
        : "r"(a[0]),"r"(a[1]),"r"(a[2]),"r"(a[3]), "r"(b[0]),"r"(b[1]));
}
__device__ __forceinline__ unsigned pkbf(float x, float y){
    __nv_bfloat162 h = __floats2bfloat162_rn(x, y);
    return *(unsigned*)&h;
}

// ---- LN of s ----
__global__ __launch_bounds__(256) void k_ln_s(const float* __restrict__ s,
                                              const float* __restrict__ w,
                                              const float* __restrict__ b){
    int i = blockIdx.x, t = threadIdx.x;
    float x = s[i*CS + t];
    __shared__ float sh[8]; __shared__ float s_m, s_r;
    float v = x;
    #pragma unroll
    for (int o=16;o;o>>=1) v += __shfl_xor_sync(~0u,v,o);
    if ((t&31)==0) sh[t>>5]=v;
    __syncthreads();
    if (t==0){ float u=0; for(int kk=0;kk<8;kk++)u+=sh[kk]; s_m=u*(1.f/256.f); }
    __syncthreads();
    float d = x - s_m; v = d*d;
    #pragma unroll
    for (int o=16;o;o>>=1) v += __shfl_xor_sync(~0u,v,o);
    if ((t&31)==0) sh[t>>5]=v;
    __syncthreads();
    if (t==0){ float u=0; for(int kk=0;kk<8;kk++)u+=sh[kk]; s_r=rsqrtf(u*(1.f/256.f)+1e-5f); }
    __syncthreads();
    g_sln[i*CS+t] = d*s_r*w[t] + b[t];
}

// ---- premix: B fragment table (bf16 split) + T1/T0 ----
__global__ void k_premix(const float* __restrict__ lnw, const float* __restrict__ lnb,
                         const float* __restrict__ Wpb, const float* __restrict__ Wpo){
    int idx = blockIdx.x*256 + threadIdx.x;
    if (idx < 2560){
        int breg = idx & 1;
        int r    = idx >> 1;
        int lane = r & 31;
        int q    = r >> 5;
        int nt   = q % 5;
        int kt   = q / 5;
        int g  = lane >> 2, t4 = lane & 3;
        int k  = kt*16 + t4*2 + breg*8;
        int n  = nt*8 + g;
        float w0 = lnw[k]  *((n<8)?Wpb[k*8+n]    :Wpo[k*32+n-8]);
        float w1 = lnw[k+1]*((n<8)?Wpb[(k+1)*8+n]:Wpo[(k+1)*32+n-8]);
        __nv_bfloat16 h0 = __float2bfloat16(w0), h1 = __float2bfloat16(w1);
        float l0 = w0 - __bfloat162float(h0), l1 = w1 - __bfloat162float(h1);
        g_Bfrag[idx]        = pkbf(__bfloat162float(h0), __bfloat162float(h1));
        g_Bfrag[2560 + idx] = pkbf(l0, l1);
    } else if (idx < 2600){
        int n = idx-2560;
        float t1=0.f, t0=0.f;
        for(int c=0;c<CZ;c++){
            float wv = (n<8)?Wpb[c*8+n]:Wpo[c*32+n-8];
            t1 += lnw[c]*wv; t0 += lnb[c]*wv;
        }
        g_T1[n]=t1; g_T0[n]=t0;
    }
}

// ---- concat projection weights ----
__global__ __launch_bounds__(256) void k_wcat(const float* __restrict__ Wq, const float* __restrict__ Wk,
                                              const float* __restrict__ Wv, const float* __restrict__ Wqp,
                                              const float* __restrict__ Wkp, const float* __restrict__ Wvp){
    int idx = blockIdx.x*256 + threadIdx.x;
    int k = idx/NPROJ, n = idx%NPROJ;
    float v;
    if      (n < 256)  v = Wq [k*256 + n];
    else if (n < 512)  v = Wk [k*256 + n-256];
    else if (n < 768)  v = Wv [k*256 + n-512];
    else if (n < 864)  v = Wqp[k*96  + n-768];
    else if (n < 960)  v = Wkp[k*96  + n-864];
    else               v = Wvp[k*192 + n-960];
    g_Wcat[idx] = v;
}

// ---- SGEMM 64x64 (projection) ----
__global__ __launch_bounds__(256) void k_sgemm2(const float* __restrict__ A,
                                                const float* __restrict__ W,
                                                const float* __restrict__ bias,
                                                const float* __restrict__ msk,
                                                float* __restrict__ C,
                                                int M, int N, int K){
    __shared__ float As[16][68], Bs[16][68];
    int tid = threadIdx.x;
    int tx = tid&15, ty = tid>>4;
    const float* Ab = A + (long)(blockIdx.y*64)*K;
    const float* Wb = W + blockIdx.x*64;
    float acc[4][4];
    #pragma unroll
    for(int u=0;u<4;u++)
        #pragma unroll
        for(int w2=0;w2<4;w2++) acc[u][w2]=0.f;

    int ar = tid>>2, ak = (tid&3)*4;
    int bk = tid>>4, bn = (tid&15)*4;
    float4 a4 = *(const float4*)&Ab[ar*K + ak];
    float4 b4 = *(const float4*)&Wb[(long)bk*N + bn];

    for(int k0=0;k0<K;k0+=16){
        As[ak+0][ar]=a4.x; As[ak+1][ar]=a4.y; As[ak+2][ar]=a4.z; As[ak+3][ar]=a4.w;
        *(float4*)&Bs[bk][bn]=b4;
        __syncthreads();
        if (k0+16 < K){
            a4 = *(const float4*)&Ab[ar*K + k0+16 + ak];
            b4 = *(const float4*)&Wb[(long)(k0+16+bk)*N + bn];
        }
        #pragma unroll
        for(int kk=0;kk<16;kk++){
            float4 av=*(const float4*)&As[kk][ty*4];
            float4 bv=*(const float4*)&Bs[kk][tx*4];
            float aa[4]={av.x,av.y,av.z,av.w};
            float bb[4]={bv.x,bv.y,bv.z,bv.w};
            #pragma unroll
            for(int u=0;u<4;u++)
                #pragma unroll
                for(int w2=0;w2<4;w2++) acc[u][w2] += aa[u]*bb[w2];
        }
        __syncthreads();
    }
    int gm0 = blockIdx.y*64 + ty*4, gn0 = blockIdx.x*64 + tx*4;
    #pragma unroll
    for(int u=0;u<4;u++){
        int gm = gm0+u;
        float mv = msk ? msk[gm] : 1.f;
        #pragma unroll
        for(int w2=0;w2<4;w2++){
            int gn = gn0+w2;
            float vv = acc[u][w2];
            if (bias) vv += bias[gn];
            C[(long)gm*N+gn] = vv*mv;
        }
    }
}

// ---- SGEMM 32x64 tiles (final projection) ----
__global__ __launch_bounds__(256) void k_sgemm3(const float* __restrict__ A,
                                                const float* __restrict__ W,
                                                const float* __restrict__ bias,
                                                const float* __restrict__ msk,
                                                float* __restrict__ C,
                                                int M, int N, int K){
    __shared__ float As[16][36], Bs[16][68];
    int tid = threadIdx.x;
    int tx = tid&15, ty = tid>>4;
    const float* Ab = A + (long)(blockIdx.y*32)*K;
    const float* Wb = W + blockIdx.x*64;
    float acc[2][4];
    #pragma unroll
    for(int u=0;u<2;u++)
        #pragma unroll
        for(int w2=0;w2<4;w2++) acc[u][w2]=0.f;

    int ar = tid>>3, ak = (tid&7)*2;
    int bk = tid>>4, bn = (tid&15)*4;
    float2 a2 = *(const float2*)&Ab[ar*K + ak];
    float4 b4 = *(const float4*)&Wb[(long)bk*N + bn];

    for(int k0=0;k0<K;k0+=16){
        As[ak+0][ar]=a2.x; As[ak+1][ar]=a2.y;
        *(float4*)&Bs[bk][bn]=b4;
        __syncthreads();
        if (k0+16 < K){
            a2 = *(const float2*)&Ab[ar*K + k0+16 + ak];
            b4 = *(const float4*)&Wb[(long)(k0+16+bk)*N + bn];
        }
        #pragma unroll
        for(int kk=0;kk<16;kk++){
            float2 av=*(const float2*)&As[kk][ty*2];
            float4 bv=*(const float4*)&Bs[kk][tx*4];
            float bb[4]={bv.x,bv.y,bv.z,bv.w};
            #pragma unroll
            for(int w2=0;w2<4;w2++){ acc[0][w2]+=av.x*bb[w2]; acc[1][w2]+=av.y*bb[w2]; }
        }
        __syncthreads();
    }
    int gm0 = blockIdx.y*32 + ty*2, gn0 = blockIdx.x*64 + tx*4;
    #pragma unroll
    for(int u=0;u<2;u++){
        int gm = gm0+u;
        float mv = msk ? msk[gm] : 1.f;
        #pragma unroll
        for(int w2=0;w2<4;w2++){
            int gn = gn0+w2;
            float vv = acc[u][w2];
            if (bias) vv += bias[gn];
            C[(long)gm*N+gn] = vv*mv;
        }
    }
}

// ---- transpose k ----
__global__ __launch_bounds__(256) void k_transpose_k(){
    __shared__ float tile[32][33];
    int c0=blockIdx.x*32, j0=blockIdx.y*32;
    int tx=threadIdx.x&31, ty=threadIdx.x>>5;
    for(int r=ty;r<32;r+=8) tile[r][tx]=g_proj[(j0+r)*NPROJ + OFF_K + c0+tx];
    __syncthreads();
    for(int r=ty;r<32;r+=8) g_kt[(c0+r)*LL+j0+tx]=tile[tx][r];
}

// ---- rigid transform ----
__global__ __launch_bounds__(128) void k_transform(const float* __restrict__ R,
                                                   const float* __restrict__ t){
    int i=blockIdx.x, tid=threadIdx.x;
    __shared__ float Rl[9], tl[3];
    if(tid<9) Rl[tid]=R[i*9+tid];
    if(tid<3) tl[tid]=t[i*3+tid];
    __syncthreads();
    if (tid<32){
        const float* src = g_proj + i*NPROJ + OFF_QPL + tid*3;
        float p0=src[0], p1=src[1], p2=src[2];
        float gx=Rl[0]*p0+Rl[1]*p1+Rl[2]*p2+tl[0];
        float gy=Rl[3]*p0+Rl[4]*p1+Rl[5]*p2+tl[1];
        float gz=Rl[6]*p0+Rl[7]*p1+Rl[8]*p2+tl[2];
        g_qpg[i*96+tid*3]=gx; g_qpg[i*96+tid*3+1]=gy; g_qpg[i*96+tid*3+2]=gz;
        float sq=gx*gx+gy*gy+gz*gz;
        sq += __shfl_xor_sync(~0u,sq,1); sq += __shfl_xor_sync(~0u,sq,2);
        if((tid&3)==0) g_qn[i*NH+(tid>>2)]=sq;
    } else if (tid<64){
        int idx=tid-32;
        const float* src = g_proj + i*NPROJ + OFF_KPL + idx*3;
        float p0=src[0], p1=src[1], p2=src[2];
        float gx=Rl[0]*p0+Rl[1]*p1+Rl[2]*p2+tl[0];
        float gy=Rl[3]*p0+Rl[4]*p1+Rl[5]*p2+tl[1];
        float gz=Rl[6]*p0+Rl[7]*p1+Rl[8]*p2+tl[2];
        g_kpgt[(idx*3+0)*LL+i]=gx; g_kpgt[(idx*3+1)*LL+i]=gy; g_kpgt[(idx*3+2)*LL+i]=gz;
        float sq=gx*gx+gy*gy+gz*gz;
        sq += __shfl_xor_sync(~0u,sq,1); sq += __shfl_xor_sync(~0u,sq,2);
        if((idx&3)==0) g_knt[(idx>>2)*LL+i]=sq;
    } else {
        int idx=tid-64;
        const float* src = g_proj + i*NPROJ + OFF_VPL + idx*3;
        float p0=src[0], p1=src[1], p2=src[2];
        g_vpg[i*192+idx*3+0]=Rl[0]*p0+Rl[1]*p1+Rl[2]*p2+tl[0];
        g_vpg[i*192+idx*3+1]=Rl[3]*p0+Rl[4]*p1+Rl[5]*p2+tl[1];
        g_vpg[i*192+idx*3+2]=Rl[6]*p0+Rl[7]*p1+Rl[8]*p2+tl[2];
    }
}

// ---- z pass on HMMA: z streamed (__ldcs), pv streamed out (__stcs) ----
__global__ __launch_bounds__(256) void k_zpass_mma(const float* __restrict__ z){
    extern __shared__ __align__(16) char smem[];
    unsigned* AH = (unsigned*)(smem + OFF_AH);
    unsigned* AL = (unsigned*)(smem + OFF_AL);
    unsigned* BF = (unsigned*)(smem + OFF_BF);
    unsigned* BL = (unsigned*)(smem + OFF_BFL);
    float* SUM = (float*)(smem + OFF_SUM);
    float* SQ  = (float*)(smem + OFF_SQ);
    float* T1s = (float*)(smem + OFF_T1S);
    float* T0s = (float*)(smem + OFF_T0S);
    int tid=threadIdx.x, wid=tid>>5, lane=tid&31;
    long pair0=(long)blockIdx.x*ZROWS;
    int irow=(int)(pair0/LL), j0=(int)(pair0%LL);

    if (tid<40){ T1s[tid]=g_T1[tid]; T0s[tid]=g_T0[tid]; }
    {
        const uint4* src=(const uint4*)g_Bfrag;
        uint4* dst=(uint4*)BF;
        #pragma unroll
        for(int l=0;l<5;l++) dst[tid + l*256] = src[tid + l*256];
    }
    {
        int ktp = lane>>2;
        #pragma unroll 4
        for(int f=0;f<16;f++){
            int row = f*8 + wid;
            float4 v = __ldcs((const float4*)&z[(pair0+row)*CZ + lane*4]);
            float s4 = v.x+v.y+v.z+v.w;
            float q4 = v.x*v.x+v.y*v.y+v.z*v.z+v.w*v.w;
            #pragma unroll
            for(int o=16;o;o>>=1){ s4+=__shfl_xor_sync(~0u,s4,o); q4+=__shfl_xor_sync(~0u,q4,o); }
            if(lane==0){ SUM[row]=s4; SQ[row]=q4; }
            int i4 = row & 15, ih = i4>>3, gg = row & 7, mt = row>>4;
            int base = (mt*8+ktp)*132;
            {
                int j = (lane*4) & 15;
                int t4 = (j&7)>>1, reg = ih + 2*(j>>3);
                int w = base + (gg*4+t4)*4 + reg;
                __nv_bfloat16 h0=__float2bfloat16(v.x), h1=__float2bfloat16(v.y);
                AH[w] = pkbf(__bfloat162float(h0), __bfloat162float(h1));
                AL[w] = pkbf(v.x-__bfloat162float(h0), v.y-__bfloat162float(h1));
            }
            {
                int j = (lane*4+2) & 15;
                int t4 = (j&7)>>1, reg = ih + 2*(j>>3);
                int w = base + (gg*4+t4)*4 + reg;
                __nv_bfloat16 h0=__float2bfloat16(v.z), h1=__float2bfloat16(v.w);
                AH[w] = pkbf(__bfloat162float(h0), __bfloat162float(h1));
                AL[w] = pkbf(v.z-__bfloat162float(h0), v.w-__bfloat162float(h1));
            }
        }
    }
    __syncthreads();

    float acc[5][4];
    #pragma unroll
    for(int nt=0;nt<5;nt++)
        #pragma unroll
        for(int u=0;u<4;u++) acc[nt][u]=0.f;
    int mt = wid;
    #pragma unroll
    for(int kt=0;kt<8;kt++){
        unsigned ah[4], al[4];
        *(uint4*)ah = *(const uint4*)&AH[(mt*8+kt)*132 + lane*4];
        *(uint4*)al = *(const uint4*)&AL[(mt*8+kt)*132 + lane*4];
        #pragma unroll
        for(int nt=0;nt<5;nt++){
            unsigned bh[2], bl[2];
            int bidx = ((kt*5+nt)*32 + lane)*2;
            *(uint2*)bh = *(const uint2*)&BF[bidx];
            *(uint2*)bl = *(const uint2*)&BL[bidx];
            mma16816(acc[nt], ah, bh);
            mma16816(acc[nt], ah, bl);
            mma16816(acc[nt], al, bh);
        }
    }

    {
        int fg = lane>>2, ft4 = lane&3;
        int r0 = mt*16 + fg, r1 = r0 + 8;
        float m0 = SUM[r0]*(1.f/128.f), m1 = SUM[r1]*(1.f/128.f);
        float rs0 = rsqrtf(SQ[r0]*(1.f/128.f) - m0*m0 + 1e-5f);
        float rs1 = rsqrtf(SQ[r1]*(1.f/128.f) - m1*m1 + 1e-5f);
        #pragma unroll
        for(int nt=0;nt<5;nt++){
            int n0 = nt*8 + ft4*2;
            float o00 = rs0*(acc[nt][0] - m0*T1s[n0])   + T0s[n0];
            float o01 = rs0*(acc[nt][1] - m0*T1s[n0+1]) + T0s[n0+1];
            float o10 = rs1*(acc[nt][2] - m1*T1s[n0])   + T0s[n0];
            float o11 = rs1*(acc[nt][3] - m1*T1s[n0+1]) + T0s[n0+1];
            if (nt==0){
                g_pb[((long)n0*LL+irow)*LL + j0 + r0]     = o00;
                g_pb[((long)(n0+1)*LL+irow)*LL + j0 + r0] = o01;
                g_pb[((long)n0*LL+irow)*LL + j0 + r1]     = o10;
                g_pb[((long)(n0+1)*LL+irow)*LL + j0 + r1] = o11;
            } else {
                __stcs((float2*)&g_pv[(pair0+r0)*32 + n0-8], make_float2(o00,o01));
                __stcs((float2*)&g_pv[(pair0+r1)*32 + n0-8], make_float2(o10,o11));
            }
        }
    }
}

// ---- fused logits + softmax -> attn ----
__global__ __launch_bounds__(256) void k_logits_softmax(const float* __restrict__ mask,
                                                        const float* __restrict__ pweights,
                                                        float* __restrict__ attn){
    int h=blockIdx.y, i0=blockIdx.x*4, tid=threadIdx.x;
    __shared__ float qv[4][32], qp[4][12], qnv[4], mi[4], red[8][4], bmax[4], brcp[4], s_pw;
    if(tid<128){ int ii=tid>>5, c=tid&31; qv[ii][c]=g_proj[(i0+ii)*NPROJ + OFF_Q + h*32+c]; }
    else if(tid<176){ int l=tid-128, ii=l/12, pp=l%12; qp[ii][pp]=g_qpg[(i0+ii)*96+h*12+pp]; }
    else if(tid<180){ int ii=tid-176; qnv[ii]=g_qn[(i0+ii)*NH+h]; mi[ii]=mask[i0+ii]; }
    else if(tid==180){ float xw=pweights[h]; s_pw=0.5f*log1pf(expf(xw)); }
    __syncthreads();

    float lv[3][4];
    const float invs = 0.17677669529663687f;
    #pragma unroll
    for(int jj=0;jj<3;jj++){
        int j=jj*256+tid;
        float sl[4]={0,0,0,0};
        const float* kt = g_kt + h*32*LL + j;
        #pragma unroll
        for(int c=0;c<32;c++){
            float kc=kt[c*LL];
            sl[0]+=qv[0][c]*kc; sl[1]+=qv[1][c]*kc; sl[2]+=qv[2][c]*kc; sl[3]+=qv[3][c]*kc;
        }
        float pd[4]={0,0,0,0};
        const float* kp = g_kpgt + h*12*LL + j;
        #pragma unroll
        for(int pp=0;pp<12;pp++){
            float kc=kp[pp*LL];
            pd[0]+=qp[0][pp]*kc; pd[1]+=qp[1][pp]*kc; pd[2]+=qp[2][pp]*kc; pd[3]+=qp[3][pp]*kc;
        }
        float knj=g_knt[h*LL+j], mj=mask[j];
        const float* pbp = g_pb + ((long)h*LL+i0)*LL + j;
        #pragma unroll
        for(int ii=0;ii<4;ii++){
            float lg = sl[ii]*invs + pbp[(long)ii*LL] - s_pw*(qnv[ii]+knj-2.f*pd[ii]);
            if (mi[ii]*mj==0.f) lg=-1e9f;
            lv[jj][ii]=lg;
        }
    }
    #pragma unroll
    for(int ii=0;ii<4;ii++){
        float m=fmaxf(fmaxf(lv[0][ii],lv[1][ii]),lv[2][ii]);
        #pragma unroll
        for(int o=16;o;o>>=1) m=fmaxf(m,__shfl_xor_sync(~0u,m,o));
        if((tid&31)==0) red[tid>>5][ii]=m;
    }
    __syncthreads();
    if(tid<4){ float m=red[0][tid]; for(int w=1;w<8;w++)m=fmaxf(m,red[w][tid]); bmax[tid]=m; }
    __syncthreads();
    float ev[3][4], sm[4]={0,0,0,0};
    #pragma unroll
    for(int jj=0;jj<3;jj++)
        #pragma unroll
        for(int ii=0;ii<4;ii++){ float e=__expf(lv[jj][ii]-bmax[ii]); ev[jj][ii]=e; sm[ii]+=e; }
    __syncthreads();
    #pragma unroll
    for(int ii=0;ii<4;ii++){
        float s=sm[ii];
        #pragma unroll
        for(int o=16;o;o>>=1) s+=__shfl_xor_sync(~0u,s,o);
        if((tid&31)==0) red[tid>>5][ii]=s;
    }
    __syncthreads();
    if(tid<4){ float s=0; for(int w=0;w<8;w++)s+=red[w][tid]; brcp[tid]=1.f/s; }
    __syncthreads();
    #pragma unroll
    for(int jj=0;jj<3;jj++){
        int j=jj*256+tid;
        #pragma unroll
        for(int ii=0;ii<4;ii++)
            attn[((long)h*LL+i0+ii)*LL+j]=ev[jj][ii]*brcp[ii];
    }
}

// ---- fused attn @ [V | v_pts_global], V transposed in smem, float2 over j ----
__global__ __launch_bounds__(256) void k_attn_fused(const float* __restrict__ attn,
                                                    const float* __restrict__ V1,
                                                    const float* __restrict__ V2){
    int h=blockIdx.y, i0=blockIdx.x*16, tid=threadIdx.x;
    __shared__ float As[16][34], Vs[64][34];
    int n=tid&63, iw=tid>>6;
    float a0=0.f,a1=0.f,a2=0.f,a3=0.f;
    for(int j0=0;j0<LL;j0+=32){
        for(int l=tid;l<512;l+=256){
            int r=l>>5, jj=l&31;
            As[r][jj]=attn[((long)h*LL+i0+r)*LL+j0+jj];
        }
        for(int l=tid;l<2048;l+=256){
            int r=l>>6, c=l&63;
            float v;
            if (c<32)      v = V1[(long)(j0+r)*NPROJ + h*32 + c];
            else if (c<56) v = V2[(long)(j0+r)*192   + h*24 + (c-32)];
            else           v = 0.f;
            Vs[c][r]=v;
        }
        __syncthreads();
        #pragma unroll
        for(int jj=0;jj<32;jj+=2){
            float2 vv = *(const float2*)&Vs[n][jj];
            float2 b0 = *(const float2*)&As[iw][jj];
            float2 b1 = *(const float2*)&As[iw+4][jj];
            float2 b2 = *(const float2*)&As[iw+8][jj];
            float2 b3 = *(const float2*)&As[iw+12][jj];
            a0 += b0.x*vv.x + b0.y*vv.y;
            a1 += b1.x*vv.x + b1.y*vv.y;
            a2 += b2.x*vv.x + b2.y*vv.y;
            a3 += b3.x*vv.x + b3.y*vv.y;
        }
        __syncthreads();
    }
    if (n<32){
        g_feat[(i0+iw)   *FEAT + h*32+n]=a0;
        g_feat[(i0+iw+4) *FEAT + h*32+n]=a1;
        g_feat[(i0+iw+8) *FEAT + h*32+n]=a2;
        g_feat[(i0+iw+12)*FEAT + h*32+n]=a3;
    } else if (n<56){
        int c=n-32;
        g_ptg[(i0+iw)   *192 + h*24+c]=a0;
        g_ptg[(i0+iw+4) *192 + h*24+c]=a1;
        g_ptg[(i0+iw+8) *192 + h*24+c]=a2;
        g_ptg[(i0+iw+12)*192 + h*24+c]=a3;
    }
}

// ---- pair_out (pv streamed in) ----
__global__ __launch_bounds__(256) void k_pair_out(const float* __restrict__ attn){
    int i=blockIdx.x, tid=threadIdx.x;
    int o=tid&31, jw=tid>>5, h=o>>2;
    float acc=0.f;
    for(int j=jw;j<LL;j+=8)
        acc += attn[((long)h*LL+i)*LL+j]*__ldcs(&g_pv[((long)i*LL+j)*32+o]);
    __shared__ float red[8][32];
    red[jw][o]=acc;
    __syncthreads();
    if(tid<32){
        float s=0; for(int w=0;w<8;w++)s+=red[w][tid];
        g_feat[i*FEAT+512+tid]=s;
    }
}

// ---- back to local frame + norms ----
__global__ __launch_bounds__(64) void k_local(const float* __restrict__ R,
                                              const float* __restrict__ t){
    int i=blockIdx.x, tid=threadIdx.x;
    __shared__ float Rl[9], tl[3];
    if(tid<9) Rl[tid]=R[i*9+tid];
    if(tid<3) tl[tid]=t[i*3+tid];
    __syncthreads();
    float gx=g_ptg[i*192+tid*3]  -tl[0];
    float gy=g_ptg[i*192+tid*3+1]-tl[1];
    float gz=g_ptg[i*192+tid*3+2]-tl[2];
    float lx=Rl[0]*gx+Rl[3]*gy+Rl[6]*gz;
    float ly=Rl[1]*gx+Rl[4]*gy+Rl[7]*gz;
    float lz=Rl[2]*gx+Rl[5]*gy+Rl[8]*gz;
    g_feat[i*FEAT+256+tid*3]  =lx;
    g_feat[i*FEAT+256+tid*3+1]=ly;
    g_feat[i*FEAT+256+tid*3+2]=lz;
    g_feat[i*FEAT+448+tid]=sqrtf(lx*lx+ly*ly+lz*lz+1e-8f);
}

extern "C" void kernel_launch(void* const* d_in, const int* in_sizes, int n_in,
                              void* d_out, int out_size){
    const float* s      =(const float*)d_in[0];
    const float* z      =(const float*)d_in[1];
    const float* R      =(const float*)d_in[2];
    const float* t      =(const float*)d_in[3];
    const float* mask   =(const float*)d_in[4];
    const float* ln_s_w =(const float*)d_in[5];
    const float* ln_s_b =(const float*)d_in[6];
    const float* ln_z_w =(const float*)d_in[7];
    const float* ln_z_b =(const float*)d_in[8];
    const float* Wq     =(const float*)d_in[9];
    const float* Wk     =(const float*)d_in[10];
    const float* Wv     =(const float*)d_in[11];
    const float* Wpb    =(const float*)d_in[12];
    const float* Wq_pts =(const float*)d_in[13];
    const float* Wk_pts =(const float*)d_in[14];
    const float* Wv_pts =(const float*)d_in[15];
    const float* pw     =(const float*)d_in[16];
    const float* Wpo    =(const float*)d_in[17];
    const float* W_out  =(const float*)d_in[18];
    const float* b_out  =(const float*)d_in[19];
    float* out  = (float*)d_out;
    float* attn = out + ATTN_OFF;

    float *p_sln,*p_wcat,*p_proj,*p_vpg,*p_feat;
    cudaGetSymbolAddress((void**)&p_sln,  g_sln);
    cudaGetSymbolAddress((void**)&p_wcat, g_Wcat);
    cudaGetSymbolAddress((void**)&p_proj, g_proj);
    cudaGetSymbolAddress((void**)&p_vpg,  g_vpg);
    cudaGetSymbolAddress((void**)&p_feat, g_feat);

    static cudaStream_t sB = nullptr;
    static cudaEvent_t evF1=nullptr, evJ1=nullptr, evF2=nullptr, evJ2=nullptr;
    if (sB == nullptr){
        cudaStreamCreateWithFlags(&sB, cudaStreamNonBlocking);
        cudaEventCreateWithFlags(&evF1, cudaEventDisableTiming);
        cudaEventCreateWithFlags(&evJ1, cudaEventDisableTiming);
        cudaEventCreateWithFlags(&evF2, cudaEventDisableTiming);
        cudaEventCreateWithFlags(&evJ2, cudaEventDisableTiming);
        cudaFuncSetAttribute(k_zpass_mma, cudaFuncAttributeMaxDynamicSharedMemorySize, SMEM_Z);
    }

    // fork 1: projection chain (sB) || z pass (s0)
    cudaEventRecord(evF1, 0);
    cudaStreamWaitEvent(sB, evF1, 0);

    k_ln_s<<<LL,256,0,sB>>>(s, ln_s_w, ln_s_b);
    k_wcat<<<(CS*NPROJ)/256,256,0,sB>>>(Wq, Wk, Wv, Wq_pts, Wk_pts, Wv_pts);
    k_sgemm2<<<dim3(NPROJ/64, LL/64),256,0,sB>>>(p_sln, p_wcat, nullptr, nullptr, p_proj, LL, NPROJ, CS);
    k_transpose_k<<<dim3(8,24),256,0,sB>>>();
    k_transform<<<LL,128,0,sB>>>(R, t);
    cudaEventRecord(evJ1, sB);

    k_premix<<<11,256>>>(ln_z_w, ln_z_b, Wpb, Wpo);
    k_zpass_mma<<<(LL*LL)/ZROWS,256,SMEM_Z>>>(z);

    cudaStreamWaitEvent(0, evJ1, 0);
    k_logits_softmax<<<dim3(LL/4,NH),256>>>(mask, pw, attn);

    // fork 2: attn_fused + local (sB) || pair_out (s0)
    cudaEventRecord(evF2, 0);
    cudaStreamWaitEvent(sB, evF2, 0);
    k_attn_fused<<<dim3(LL/16,NH),256,0,sB>>>(attn, p_proj + OFF_V, p_vpg);
    k_local<<<LL,64,0,sB>>>(R, t);
    cudaEventRecord(evJ2, sB);

    k_pair_out<<<LL,256>>>(attn);

    cudaStreamWaitEvent(0, evJ2, 0);
    k_sgemm3<<<dim3(CS/64, LL/32),256>>>(p_feat, W_out, b_out, mask, out, LL, CS, FEAT);
}